// round 1
// baseline (speedup 1.0000x reference)
#include <cuda_runtime.h>

#define N_NODES 20000
#define N_ATTRS 5000
#define IN_F 512
#define OUT_F 128
#define LRELU_ALPHA 0.2f
#define TM 64
#define TJ 32

typedef unsigned long long ull;

// Scratch (no cudaMalloc allowed)
__device__ __align__(16) float g_v1[IN_F];                        // W @ a1
__device__ __align__(16) float g_attr_h[(size_t)N_ATTRS * OUT_F]; // attr projections
__device__ __align__(16) float g_P[N_NODES];                      // exp(s_i)
__device__ __align__(16) float g_Pa[N_NODES];                     // exp(alpha*s_i)
__device__ __align__(16) float g_Q[N_ATTRS];                      // exp(t_j)
__device__ __align__(16) float g_Qa[N_ATTRS];                     // exp(alpha*t_j)

// ---- packed fp32x2 helpers (Blackwell FFMA2: 2x fp32 throughput) ----
__device__ __forceinline__ ull pack2(float x) {
    ull r; asm("mov.b64 %0, {%1, %1};" : "=l"(r) : "f"(x)); return r;
}
__device__ __forceinline__ void ffma2(ull& d, ull a, ull b) {
    asm("fma.rn.f32x2 %0, %1, %2, %0;" : "+l"(d) : "l"(a), "l"(b));
}
__device__ __forceinline__ float2 unpack2(ull v) {
    float2 r; asm("mov.b64 {%0, %1}, %2;" : "=f"(r.x), "=f"(r.y) : "l"(v)); return r;
}

// K1: v1[k] = sum_f W[k][f] * a1[f]
__global__ void k_v1(const float* __restrict__ W, const float* __restrict__ a) {
    __shared__ float sa[OUT_F];
    if (threadIdx.x < OUT_F) sa[threadIdx.x] = a[threadIdx.x];
    __syncthreads();
    int k = blockIdx.x * blockDim.x + threadIdx.x;
    if (k < IN_F) {
        const float* wr = W + (size_t)k * OUT_F;
        float s = 0.f;
        #pragma unroll 16
        for (int f = 0; f < OUT_F; f++) s += wr[f] * sa[f];
        g_v1[k] = s;
    }
}

// K2: one warp per node row: s_i = node_emb[i] . v1 ; P = exp(s), Pa = exp(alpha*s)
__global__ void k_node(const float* __restrict__ ne) {
    int gw = (blockIdx.x * blockDim.x + threadIdx.x) >> 5;
    int lane = threadIdx.x & 31;
    if (gw >= N_NODES) return;
    const float4* row = (const float4*)(ne + (size_t)gw * IN_F);
    const float4* v1 = (const float4*)g_v1;
    float s = 0.f;
    #pragma unroll
    for (int t = 0; t < 4; t++) {
        float4 x = row[lane + 32 * t];
        float4 c = v1[lane + 32 * t];
        s += x.x * c.x + x.y * c.y + x.z * c.z + x.w * c.w;
    }
    #pragma unroll
    for (int o = 16; o > 0; o >>= 1) s += __shfl_xor_sync(0xffffffffu, s, o);
    if (lane == 0) {
        g_P[gw]  = expf(s);
        g_Pa[gw] = expf(LRELU_ALPHA * s);
    }
}

// K3: attr_h = attr_emb @ W  (64x128 tile per CTA) + t_j = attr_h . a2 -> Q, Qa
__global__ void k_attr(const float* __restrict__ ae, const float* __restrict__ Wm,
                       const float* __restrict__ a) {
    __shared__ float sA[64][32];
    __shared__ float sW[32][OUT_F];
    int tid = threadIdx.x;
    int r0 = blockIdx.x * 64;
    int wr = tid >> 5;    // warp -> rows wr*8 .. wr*8+7
    int lane = tid & 31;  // lane -> cols lane*4 .. lane*4+3
    float acc[8][4];
    #pragma unroll
    for (int i = 0; i < 8; i++)
        #pragma unroll
        for (int c = 0; c < 4; c++) acc[i][c] = 0.f;

    for (int k0 = 0; k0 < IN_F; k0 += 32) {
        __syncthreads();
        #pragma unroll
        for (int it = 0; it < 8; it++) {
            int idx = tid + 256 * it;
            int r = idx >> 5, kk = idx & 31;
            int gr = r0 + r;
            sA[r][kk] = (gr < N_ATTRS) ? ae[(size_t)gr * IN_F + k0 + kk] : 0.f;
        }
        #pragma unroll
        for (int it = 0; it < 4; it++) {
            int idx = tid + 256 * it;
            int kk = idx >> 5, f4 = idx & 31;
            *(float4*)&sW[kk][f4 * 4] = *(const float4*)(Wm + (size_t)(k0 + kk) * OUT_F + f4 * 4);
        }
        __syncthreads();
        #pragma unroll 8
        for (int kk = 0; kk < 32; kk++) {
            float4 wv = *(float4*)&sW[kk][lane * 4];
            #pragma unroll
            for (int r = 0; r < 8; r++) {
                float av = sA[wr * 8 + r][kk];
                acc[r][0] += av * wv.x;
                acc[r][1] += av * wv.y;
                acc[r][2] += av * wv.z;
                acc[r][3] += av * wv.w;
            }
        }
    }
    float4 a2v = *(const float4*)(a + OUT_F + lane * 4);
    #pragma unroll
    for (int r = 0; r < 8; r++) {
        int gr = r0 + wr * 8 + r;
        float t = acc[r][0] * a2v.x + acc[r][1] * a2v.y + acc[r][2] * a2v.z + acc[r][3] * a2v.w;
        #pragma unroll
        for (int o = 16; o > 0; o >>= 1) t += __shfl_xor_sync(0xffffffffu, t, o);
        if (gr < N_ATTRS) {
            *(float4*)&g_attr_h[(size_t)gr * OUT_F + lane * 4] =
                make_float4(acc[r][0], acc[r][1], acc[r][2], acc[r][3]);
            if (lane == 0) {
                g_Q[gr]  = expf(t);
                g_Qa[gr] = expf(LRELU_ALPHA * t);
            }
        }
    }
}

// K4: fused masked-softmax + attention @ attr_h + ELU.
// CTA: 64 nodes x full 128 features. 128 threads, thread tile 8n x 8f (fp32x2 FMA).
// weight w_ij = m_ij * ( P_i*Q_j >= 1 ? P_i*Q_j : Pa_i*Qa_j )   [= exp(lrelu(s_i+t_j))]
__global__ __launch_bounds__(128) void k_main(const int* __restrict__ feat,
                                              float* __restrict__ out) {
    __shared__ float sP[TM], sPa[TM], sDen[TM];
    __shared__ float sWgt[TJ][TM + 1];   // [jj][n], padded: conflict-free writes
    __shared__ float sV[TJ][OUT_F];

    int tid = threadIdx.x;
    int n0 = blockIdx.x * TM;

    if (tid < TM) {
        int gn = n0 + tid;
        sP[tid]  = (gn < N_NODES) ? g_P[gn]  : 0.f;
        sPa[tid] = (gn < N_NODES) ? g_Pa[gn] : 0.f;
    }

    // weight-stage identity: thread -> (node wn, 16-wide jj half)
    const int wn = tid >> 1;
    const int jhalf = (tid & 1) << 4;
    const int gwn = n0 + wn;
    const bool nv = gwn < N_NODES;
    const int* frow = feat + (size_t)gwn * N_ATTRS;

    // FMA-stage identity: thread -> (8 features @ fx*8, 8 nodes @ ny*8)
    const int fx = tid & 15;
    const int ny = tid >> 4;

    ull acc[8][4];
    #pragma unroll
    for (int i = 0; i < 8; i++)
        #pragma unroll
        for (int p = 0; p < 4; p++) acc[i][p] = 0ull;

    float dpart = 0.f;
    __syncthreads();
    const float Pv = sP[wn], Pav = sPa[wn];

    for (int j0 = 0; j0 < N_ATTRS; j0 += TJ) {
        // ---- phase A: compute 64x32 weight tile + load 32x128 V tile ----
        #pragma unroll
        for (int g = 0; g < 4; g++) {
            int j = j0 + jhalf + g * 4;
            float w0 = 0.f, w1 = 0.f, w2 = 0.f, w3 = 0.f;
            if (nv && j < N_ATTRS) {
                int4 m    = *(const int4*)(frow + j);
                float4 q  = *(const float4*)(g_Q + j);
                float4 qa = *(const float4*)(g_Qa + j);
                float pq, w;
                pq = Pv * q.x; w = (pq >= 1.f) ? pq : Pav * qa.x; w0 = (m.x > 0) ? w : 0.f;
                pq = Pv * q.y; w = (pq >= 1.f) ? pq : Pav * qa.y; w1 = (m.y > 0) ? w : 0.f;
                pq = Pv * q.z; w = (pq >= 1.f) ? pq : Pav * qa.z; w2 = (m.z > 0) ? w : 0.f;
                pq = Pv * q.w; w = (pq >= 1.f) ? pq : Pav * qa.w; w3 = (m.w > 0) ? w : 0.f;
            }
            int jj = jhalf + g * 4;
            sWgt[jj + 0][wn] = w0; sWgt[jj + 1][wn] = w1;
            sWgt[jj + 2][wn] = w2; sWgt[jj + 3][wn] = w3;
            dpart += (w0 + w1) + (w2 + w3);
        }
        #pragma unroll
        for (int it = 0; it < 8; it++) {
            int idx = tid + 128 * it;
            int jj = idx >> 5, f4 = idx & 31;
            int j = j0 + jj;
            if (j < N_ATTRS)
                *(float4*)&sV[jj][f4 * 4] =
                    *(const float4*)(g_attr_h + (size_t)j * OUT_F + f4 * 4);
        }
        __syncthreads();
        // ---- phase B: rank-32 update, 8n x 8f per thread, fp32x2 ----
        #pragma unroll 2
        for (int jj = 0; jj < TJ; jj++) {
            const ull* vp = (const ull*)&sV[jj][fx * 8];
            ull v0 = vp[0], v1 = vp[1], v2 = vp[2], v3 = vp[3];
            #pragma unroll
            for (int i = 0; i < 8; i++) {
                ull wp = pack2(sWgt[jj][ny * 8 + i]);
                ffma2(acc[i][0], wp, v0);
                ffma2(acc[i][1], wp, v1);
                ffma2(acc[i][2], wp, v2);
                ffma2(acc[i][3], wp, v3);
            }
        }
        __syncthreads();
    }

    // denominators: pair-reduce the two jj-halves per node
    {
        float d = dpart;
        d += __shfl_xor_sync(0xffffffffu, d, 1);
        if ((tid & 1) == 0) sDen[wn] = d;
    }
    __syncthreads();

    // epilogue: normalize + ELU + store
    #pragma unroll
    for (int i = 0; i < 8; i++) {
        int n = ny * 8 + i;
        int gn = n0 + n;
        if (gn >= N_NODES) continue;
        float den = sDen[n];
        float inv = (den > 0.f) ? 1.f / den : 0.f;
        float o[8];
        #pragma unroll
        for (int p = 0; p < 4; p++) {
            float2 u = unpack2(acc[i][p]);
            o[p * 2]     = u.x * inv;
            o[p * 2 + 1] = u.y * inv;
        }
        #pragma unroll
        for (int e = 0; e < 8; e++) o[e] = (o[e] > 0.f) ? o[e] : expm1f(o[e]);
        float4* dst = (float4*)(out + (size_t)gn * OUT_F + fx * 8);
        dst[0] = make_float4(o[0], o[1], o[2], o[3]);
        dst[1] = make_float4(o[4], o[5], o[6], o[7]);
    }
}

extern "C" void kernel_launch(void* const* d_in, const int* in_sizes, int n_in,
                              void* d_out, int out_size) {
    const float* node_emb = (const float*)d_in[0];
    const float* attr_emb = (const float*)d_in[1];
    const int*   feat     = (const int*)d_in[2];
    const float* W        = (const float*)d_in[3];
    const float* a        = (const float*)d_in[4];
    float* out = (float*)d_out;

    k_v1<<<(IN_F + 255) / 256, 256>>>(W, a);
    k_node<<<(N_NODES * 32 + 255) / 256, 256>>>(node_emb);
    k_attr<<<(N_ATTRS + 63) / 64, 256>>>(attr_emb, W, a);
    k_main<<<(N_NODES + TM - 1) / TM, 128>>>(feat, out);
}

// round 3
// speedup vs baseline: 2.3044x; 2.3044x over previous
#include <cuda_runtime.h>
#include <cstdint>

#define N_NODES 20000
#define N_ATTRS 5000
#define IN_F 512
#define OUT_F 128
#define LRELU_ALPHA 0.2f
#define TM 64
#define TJ 32
#define JSPLIT 4
#define NTILE_N 313          // ceil(20000/64)
#define NTILES_GLOB 157      // ceil(5000/32)
#define SMEM_BYTES 60416

typedef unsigned long long ull;
typedef unsigned int u32;

// ---------------- scratch (no cudaMalloc allowed) ----------------
__device__ __align__(16) float g_v1[IN_F];                                 // W @ a1
__device__ __align__(16) float g_attr_h[(size_t)(N_ATTRS + TJ) * OUT_F];   // padded attr projections
__device__ __align__(16) float g_P[N_NODES];
__device__ __align__(16) float g_Pa[N_NODES];
__device__ __align__(16) float g_Q[N_ATTRS];
__device__ __align__(16) float g_Qa[N_ATTRS];
__device__ __align__(16) float g_part[(size_t)JSPLIT * N_NODES * OUT_F];   // split partial sums
__device__ __align__(16) float g_den[JSPLIT * N_NODES];                    // split partial denominators

// ---------------- helpers ----------------
__device__ __forceinline__ ull pack2(float x) {
    ull r; asm("mov.b64 %0, {%1, %1};" : "=l"(r) : "f"(x)); return r;
}
__device__ __forceinline__ void ffma2(ull& d, ull a, ull b) {
    asm("fma.rn.f32x2 %0, %1, %2, %0;" : "+l"(d) : "l"(a), "l"(b));
}
__device__ __forceinline__ float2 unpack2(ull v) {
    float2 r; asm("mov.b64 {%0, %1}, %2;" : "=f"(r.x), "=f"(r.y) : "l"(v)); return r;
}
__device__ __forceinline__ void cp_async16(u32 smem, const void* gmem) {
    asm volatile("cp.async.cg.shared.global [%0], [%1], 16;" :: "r"(smem), "l"(gmem));
}

// K1: v1[k] = sum_f W[k][f] * a1[f]
__global__ void k_v1(const float* __restrict__ W, const float* __restrict__ a) {
    __shared__ float sa[OUT_F];
    if (threadIdx.x < OUT_F) sa[threadIdx.x] = a[threadIdx.x];
    __syncthreads();
    int k = blockIdx.x * blockDim.x + threadIdx.x;
    if (k < IN_F) {
        const float* wr = W + (size_t)k * OUT_F;
        float s = 0.f;
        #pragma unroll 16
        for (int f = 0; f < OUT_F; f++) s += wr[f] * sa[f];
        g_v1[k] = s;
    }
}

// K2: one warp per node: s_i = node_emb[i].v1 ; P=exp(s), Pa=exp(alpha*s)
__global__ void k_node(const float* __restrict__ ne) {
    int gw = (blockIdx.x * blockDim.x + threadIdx.x) >> 5;
    int lane = threadIdx.x & 31;
    if (gw >= N_NODES) return;
    const float4* row = (const float4*)(ne + (size_t)gw * IN_F);
    const float4* v1 = (const float4*)g_v1;
    float s = 0.f;
    #pragma unroll
    for (int t = 0; t < 4; t++) {
        float4 x = row[lane + 32 * t];
        float4 c = v1[lane + 32 * t];
        s += x.x * c.x + x.y * c.y + x.z * c.z + x.w * c.w;
    }
    #pragma unroll
    for (int o = 16; o > 0; o >>= 1) s += __shfl_xor_sync(0xffffffffu, s, o);
    if (lane == 0) {
        g_P[gw]  = expf(s);
        g_Pa[gw] = expf(LRELU_ALPHA * s);
    }
}

// K3: attr_h = attr_emb @ W (64x128 tile/CTA) + t_j -> Q, Qa
__global__ void k_attr(const float* __restrict__ ae, const float* __restrict__ Wm,
                       const float* __restrict__ a) {
    __shared__ float sA[64][32];
    __shared__ float sW[32][OUT_F];
    int tid = threadIdx.x;
    int r0 = blockIdx.x * 64;
    int wr = tid >> 5;
    int lane = tid & 31;
    float acc[8][4];
    #pragma unroll
    for (int i = 0; i < 8; i++)
        #pragma unroll
        for (int c = 0; c < 4; c++) acc[i][c] = 0.f;

    for (int k0 = 0; k0 < IN_F; k0 += 32) {
        __syncthreads();
        #pragma unroll
        for (int it = 0; it < 8; it++) {
            int idx = tid + 256 * it;
            int r = idx >> 5, kk = idx & 31;
            int gr = r0 + r;
            sA[r][kk] = (gr < N_ATTRS) ? ae[(size_t)gr * IN_F + k0 + kk] : 0.f;
        }
        #pragma unroll
        for (int it = 0; it < 4; it++) {
            int idx = tid + 256 * it;
            int kk = idx >> 5, f4 = idx & 31;
            *(float4*)&sW[kk][f4 * 4] = *(const float4*)(Wm + (size_t)(k0 + kk) * OUT_F + f4 * 4);
        }
        __syncthreads();
        #pragma unroll 8
        for (int kk = 0; kk < 32; kk++) {
            float4 wv = *(float4*)&sW[kk][lane * 4];
            #pragma unroll
            for (int r = 0; r < 8; r++) {
                float av = sA[wr * 8 + r][kk];
                acc[r][0] += av * wv.x;
                acc[r][1] += av * wv.y;
                acc[r][2] += av * wv.z;
                acc[r][3] += av * wv.w;
            }
        }
    }
    float4 a2v = *(const float4*)(a + OUT_F + lane * 4);
    #pragma unroll
    for (int r = 0; r < 8; r++) {
        int gr = r0 + wr * 8 + r;
        float t = acc[r][0] * a2v.x + acc[r][1] * a2v.y + acc[r][2] * a2v.z + acc[r][3] * a2v.w;
        #pragma unroll
        for (int o = 16; o > 0; o >>= 1) t += __shfl_xor_sync(0xffffffffu, t, o);
        if (gr < N_ATTRS) {
            *(float4*)&g_attr_h[(size_t)gr * OUT_F + lane * 4] =
                make_float4(acc[r][0], acc[r][1], acc[r][2], acc[r][3]);
            if (lane == 0) {
                g_Q[gr]  = expf(t);
                g_Qa[gr] = expf(LRELU_ALPHA * t);
            }
        }
    }
}

// K4: fused masked-softmax-weight * attr_h, split-j partials.
// CTA: 64 nodes x 128 feats x (tiles js, js+4, js+8, ... of 32 attrs).
// 256 threads. Double-buffered (cp.async V, register-prefetched feat), 1 barrier/tile.
__global__ __launch_bounds__(256, 3) void k_main(const int* __restrict__ feat) {
    extern __shared__ char dsm[];
    float* sVf = (float*)dsm;                    // [2][32][128]
    float* sWf = (float*)(dsm + 32768);          // [2][32][66]
    float* sQ  = (float*)(dsm + 49664);          // [<=1280]
    float* sQa = (float*)(dsm + 54784);          // [<=1280]
    float* sP  = (float*)(dsm + 59904);          // [64]
    float* sPa = (float*)(dsm + 60160);          // [64]

    const int tid = threadIdx.x;
    const int js  = blockIdx.x & 3;
    const int n0  = (blockIdx.x >> 2) * TM;
    const int NT  = (NTILES_GLOB - js + 3) >> 2;   // 40,39,39,39

    if (tid < TM) {
        int gn = n0 + tid;
        sP[tid]  = (gn < N_NODES) ? g_P[gn] : 0.f;
        sPa[tid] = (gn < N_NODES) ? g_Pa[gn] : 0.f;
    }
    // compacted Q/Qa for this split's tiles
    for (int idx = tid; idx < NT * TJ; idx += 256) {
        int k = idx >> 5, jj = idx & 31;
        int j = (js + 4 * k) * TJ + jj;
        sQ[idx]  = (j < N_ATTRS) ? g_Q[j] : 0.f;
        sQa[idx] = (j < N_ATTRS) ? g_Qa[j] : 0.f;
    }
    __syncthreads();

    // weight-stage identity: 4 threads per node, 8 attrs each
    const int wn = tid >> 2, jq = tid & 3;
    const int jloc = jq * 8;
    const int gwn = n0 + wn;
    const bool nv = gwn < N_NODES;
    const int* frow = feat + (size_t)gwn * N_ATTRS;
    const float Pv = sP[wn], Pav = sPa[wn];
    // FMA-stage identity: features [fx4,fx4+4) and [64+fx4,..), nodes ny4..ny4+3
    const int fx4 = (tid & 15) * 4;
    const int ny4 = (tid >> 4) * 4;

    ull acc[4][4];
    #pragma unroll
    for (int i = 0; i < 4; i++)
        #pragma unroll
        for (int p = 0; p < 4; p++) acc[i][p] = 0ull;
    float dpart = 0.f;
    int4 fr0 = make_int4(0, 0, 0, 0), fr1 = make_int4(0, 0, 0, 0);

    auto prefetch = [&](int kt) {
        int jg = (js + 4 * kt) * TJ + jloc;
        if (nv && jg + 8 <= N_ATTRS) {
            fr0 = *(const int4*)(frow + jg);
            fr1 = *(const int4*)(frow + jg + 4);
        }
    };
    auto computeW = [&](int kt, int buf) {
        int jg = (js + 4 * kt) * TJ + jloc;
        float w[8];
        if (nv && jg + 8 <= N_ATTRS) {
            float4 q0  = *(const float4*)&sQ [kt * TJ + jloc];
            float4 q1  = *(const float4*)&sQ [kt * TJ + jloc + 4];
            float4 qa0 = *(const float4*)&sQa[kt * TJ + jloc];
            float4 qa1 = *(const float4*)&sQa[kt * TJ + jloc + 4];
            float pq;
            pq = Pv * q0.x; w[0] = (fr0.x > 0) ? ((pq >= 1.f) ? pq : Pav * qa0.x) : 0.f;
            pq = Pv * q0.y; w[1] = (fr0.y > 0) ? ((pq >= 1.f) ? pq : Pav * qa0.y) : 0.f;
            pq = Pv * q0.z; w[2] = (fr0.z > 0) ? ((pq >= 1.f) ? pq : Pav * qa0.z) : 0.f;
            pq = Pv * q0.w; w[3] = (fr0.w > 0) ? ((pq >= 1.f) ? pq : Pav * qa0.w) : 0.f;
            pq = Pv * q1.x; w[4] = (fr1.x > 0) ? ((pq >= 1.f) ? pq : Pav * qa1.x) : 0.f;
            pq = Pv * q1.y; w[5] = (fr1.y > 0) ? ((pq >= 1.f) ? pq : Pav * qa1.y) : 0.f;
            pq = Pv * q1.z; w[6] = (fr1.z > 0) ? ((pq >= 1.f) ? pq : Pav * qa1.z) : 0.f;
            pq = Pv * q1.w; w[7] = (fr1.w > 0) ? ((pq >= 1.f) ? pq : Pav * qa1.w) : 0.f;
        } else {
            #pragma unroll
            for (int i = 0; i < 8; i++) w[i] = 0.f;
        }
        float* dst = sWf + buf * 2112;
        #pragma unroll
        for (int i = 0; i < 8; i++) dst[(jloc + i) * 66 + wn] = w[i];
        dpart += ((w[0] + w[1]) + (w[2] + w[3])) + ((w[4] + w[5]) + (w[6] + w[7]));
    };
    auto loadV = [&](int kt, int buf) {
        int j0 = (js + 4 * kt) * TJ;
        u32 sbase = (u32)__cvta_generic_to_shared(sVf + buf * 4096);
        #pragma unroll
        for (int t = 0; t < 4; t++) {
            int idx = tid + 256 * t;   // 1024 float4s total
            cp_async16(sbase + idx * 16,
                       g_attr_h + (size_t)(j0 + (idx >> 5)) * OUT_F + (idx & 31) * 4);
        }
        asm volatile("cp.async.commit_group;");
    };

    // prologue: stage tile 0
    prefetch(0);
    loadV(0, 0);
    computeW(0, 0);
    asm volatile("cp.async.wait_group 0;" ::: "memory");
    __syncthreads();

    for (int k = 0; k < NT; k++) {
        int b = k & 1;
        bool hn = (k + 1) < NT;
        if (hn) { loadV(k + 1, 1 - b); prefetch(k + 1); }

        const float* sVb = sVf + b * 4096;
        const float* sWb = sWf + b * 2112;
        #pragma unroll 8
        for (int jj = 0; jj < TJ; jj++) {
            ulonglong2 vA = *(const ulonglong2*)(sVb + jj * 128 + fx4);
            ulonglong2 vB = *(const ulonglong2*)(sVb + jj * 128 + fx4 + 64);
            const float* wrow = sWb + jj * 66 + ny4;
            #pragma unroll
            for (int i = 0; i < 4; i++) {
                ull wp = pack2(wrow[i]);
                ffma2(acc[i][0], wp, vA.x);
                ffma2(acc[i][1], wp, vA.y);
                ffma2(acc[i][2], wp, vB.x);
                ffma2(acc[i][3], wp, vB.y);
            }
        }
        if (hn) computeW(k + 1, 1 - b);
        asm volatile("cp.async.wait_group 0;" ::: "memory");
        __syncthreads();
    }

    // partial denominators (4 threads per node)
    dpart += __shfl_xor_sync(0xffffffffu, dpart, 1);
    dpart += __shfl_xor_sync(0xffffffffu, dpart, 2);
    if (jq == 0 && nv) g_den[js * N_NODES + gwn] = dpart;

    // partial outputs
    float* pbase = g_part + (size_t)js * N_NODES * OUT_F;
    #pragma unroll
    for (int i = 0; i < 4; i++) {
        int gn = n0 + ny4 + i;
        if (gn >= N_NODES) continue;
        float2 a0 = unpack2(acc[i][0]), a1 = unpack2(acc[i][1]);
        float2 b0 = unpack2(acc[i][2]), b1 = unpack2(acc[i][3]);
        *(float4*)(pbase + (size_t)gn * OUT_F + fx4)      = make_float4(a0.x, a0.y, a1.x, a1.y);
        *(float4*)(pbase + (size_t)gn * OUT_F + fx4 + 64) = make_float4(b0.x, b0.y, b1.x, b1.y);
    }
}

// K5: reduce splits, normalize, ELU, store
__global__ void k_final(float* __restrict__ out) {
    int gid = blockIdx.x * blockDim.x + threadIdx.x;   // one float4 each
    int row = gid >> 5;
    int f = (gid & 31) * 4;
    if (row >= N_NODES) return;
    float4 s = make_float4(0.f, 0.f, 0.f, 0.f);
    float den = 0.f;
    #pragma unroll
    for (int sp = 0; sp < JSPLIT; sp++) {
        const float4 p = *(const float4*)(g_part + ((size_t)sp * N_NODES + row) * OUT_F + f);
        s.x += p.x; s.y += p.y; s.z += p.z; s.w += p.w;
        den += g_den[sp * N_NODES + row];
    }
    float inv = (den > 0.f) ? 1.f / den : 0.f;
    float o[4] = {s.x * inv, s.y * inv, s.z * inv, s.w * inv};
    #pragma unroll
    for (int e = 0; e < 4; e++) o[e] = (o[e] > 0.f) ? o[e] : expm1f(o[e]);
    *(float4*)(out + (size_t)row * OUT_F + f) = make_float4(o[0], o[1], o[2], o[3]);
}

extern "C" void kernel_launch(void* const* d_in, const int* in_sizes, int n_in,
                              void* d_out, int out_size) {
    const float* node_emb = (const float*)d_in[0];
    const float* attr_emb = (const float*)d_in[1];
    const int*   feat     = (const int*)d_in[2];
    const float* W        = (const float*)d_in[3];
    const float* a        = (const float*)d_in[4];
    float* out = (float*)d_out;

    cudaFuncSetAttribute(k_main, cudaFuncAttributeMaxDynamicSharedMemorySize, SMEM_BYTES);

    k_v1<<<(IN_F + 255) / 256, 256>>>(W, a);
    k_node<<<(N_NODES * 32 + 255) / 256, 256>>>(node_emb);
    k_attr<<<(N_ATTRS + 63) / 64, 256>>>(attr_emb, W, a);
    k_main<<<NTILE_N * JSPLIT, 256, SMEM_BYTES>>>(feat);
    k_final<<<(N_NODES * 32 + 255) / 256, 256>>>(out);
}

// round 5
// speedup vs baseline: 2.4946x; 1.0825x over previous
#include <cuda_runtime.h>
#include <cuda_bf16.h>
#include <cstdint>

#define N_NODES 20000
#define N_ATTRS 5000
#define IN_F 512
#define OUT_F 128
#define LRELU_ALPHA 0.2f

#define M_TILE 128
#define JT 64
#define VT_LD 5056           // padded attr count (79*64)
#define NT_J 79              // total 64-attr tiles
#define JSPLIT 4
#define TPS 20               // tiles per split (last split gets 19)
#define N_CTAS_N 157         // ceil(20000/128)
#define VROW 144             // smem V row pitch (bytes): conflict-free ldmatrix
#define VTILE (128 * VROW)   // 18432 B per (hi or lo) tile
#define SMEM_BYTES (4 * VTILE)  // 73728: double buffer x (hi+lo)

typedef unsigned long long ull;
typedef unsigned int u32;

// ---------------- scratch (no cudaMalloc allowed) ----------------
__device__ __align__(16) float g_v1[IN_F];
__device__ __align__(16) float g_attr_h[(size_t)(N_ATTRS + 64) * OUT_F];
__device__ __align__(16) float g_P[N_NODES];
__device__ __align__(16) float g_Pa[N_NODES];
__device__ __align__(16) float g_Q[VT_LD];
__device__ __align__(16) float g_Qa[VT_LD];
__device__ __align__(16) __nv_bfloat16 g_vt_hi[(size_t)OUT_F * VT_LD];
__device__ __align__(16) __nv_bfloat16 g_vt_lo[(size_t)OUT_F * VT_LD];
__device__ __align__(16) float g_part[(size_t)JSPLIT * N_NODES * OUT_F];
__device__ __align__(16) float g_den[JSPLIT * N_NODES];

// ---------------- helpers ----------------
__device__ __forceinline__ u32 smem_u32(const void* p) {
    u32 a;
    asm("{ .reg .u64 t; cvta.to.shared.u64 t, %1; cvt.u32.u64 %0, t; }" : "=r"(a) : "l"(p));
    return a;
}
__device__ __forceinline__ void cp_async16(u32 smem, const void* gmem) {
    asm volatile("cp.async.cg.shared.global [%0], [%1], 16;" :: "r"(smem), "l"(gmem));
}
#define CP_COMMIT() asm volatile("cp.async.commit_group;")

__device__ __forceinline__ u32 cvt_bf16x2(float lo, float hi) {
    u32 r;
    asm("cvt.rn.bf16x2.f32 %0, %1, %2;" : "=r"(r) : "f"(hi), "f"(lo));
    return r;
}
#define LDSM4(r0, r1, r2, r3, addr) \
    asm volatile("ldmatrix.sync.aligned.m8n8.x4.shared.b16 {%0,%1,%2,%3}, [%4];" \
        : "=r"(r0), "=r"(r1), "=r"(r2), "=r"(r3) : "r"(addr))

__device__ __forceinline__ void mma16816(float* c, u32 a0, u32 a1, u32 a2, u32 a3,
                                         u32 b0, u32 b1) {
    asm volatile("mma.sync.aligned.m16n8k16.row.col.f32.bf16.bf16.f32 "
        "{%0,%1,%2,%3}, {%4,%5,%6,%7}, {%8,%9}, {%0,%1,%2,%3};"
        : "+f"(c[0]), "+f"(c[1]), "+f"(c[2]), "+f"(c[3])
        : "r"(a0), "r"(a1), "r"(a2), "r"(a3), "r"(b0), "r"(b1));
}
__device__ __forceinline__ float wfun(int m, float P, float Pa, float q, float qa) {
    float pq = P * q;
    float w = (pq >= 1.f) ? pq : Pa * qa;
    return (m > 0) ? w : 0.f;
}

// ================= K1: v1 = W @ a1 =================
__global__ void k_v1(const float* __restrict__ W, const float* __restrict__ a) {
    __shared__ float sa[OUT_F];
    if (threadIdx.x < OUT_F) sa[threadIdx.x] = a[threadIdx.x];
    __syncthreads();
    int k = blockIdx.x * blockDim.x + threadIdx.x;
    if (k < IN_F) {
        const float* wr = W + (size_t)k * OUT_F;
        float s = 0.f;
        #pragma unroll 16
        for (int f = 0; f < OUT_F; f++) s += wr[f] * sa[f];
        g_v1[k] = s;
    }
}

// ================= K2: node scores -> P, Pa =================
__global__ void k_node(const float* __restrict__ ne) {
    int gw = (blockIdx.x * blockDim.x + threadIdx.x) >> 5;
    int lane = threadIdx.x & 31;
    if (gw >= N_NODES) return;
    const float4* row = (const float4*)(ne + (size_t)gw * IN_F);
    const float4* v1 = (const float4*)g_v1;
    float s = 0.f;
    #pragma unroll
    for (int t = 0; t < 4; t++) {
        float4 x = row[lane + 32 * t];
        float4 c = v1[lane + 32 * t];
        s += x.x * c.x + x.y * c.y + x.z * c.z + x.w * c.w;
    }
    #pragma unroll
    for (int o = 16; o > 0; o >>= 1) s += __shfl_xor_sync(0xffffffffu, s, o);
    if (lane == 0) {
        g_P[gw]  = expf(s);
        g_Pa[gw] = expf(LRELU_ALPHA * s);
    }
}

// ================= K3: attr_h = attr_emb @ W ; Q, Qa =================
__global__ void k_attr(const float* __restrict__ ae, const float* __restrict__ Wm,
                       const float* __restrict__ a) {
    __shared__ float sA[64][32];
    __shared__ float sW[32][OUT_F];
    int tid = threadIdx.x;
    int r0 = blockIdx.x * 64;
    int wr = tid >> 5;
    int lane = tid & 31;
    float acc[8][4];
    #pragma unroll
    for (int i = 0; i < 8; i++)
        #pragma unroll
        for (int c = 0; c < 4; c++) acc[i][c] = 0.f;

    for (int k0 = 0; k0 < IN_F; k0 += 32) {
        __syncthreads();
        #pragma unroll
        for (int it = 0; it < 8; it++) {
            int idx = tid + 256 * it;
            int r = idx >> 5, kk = idx & 31;
            int gr = r0 + r;
            sA[r][kk] = (gr < N_ATTRS) ? ae[(size_t)gr * IN_F + k0 + kk] : 0.f;
        }
        #pragma unroll
        for (int it = 0; it < 4; it++) {
            int idx = tid + 256 * it;
            int kk = idx >> 5, f4 = idx & 31;
            *(float4*)&sW[kk][f4 * 4] = *(const float4*)(Wm + (size_t)(k0 + kk) * OUT_F + f4 * 4);
        }
        __syncthreads();
        #pragma unroll 8
        for (int kk = 0; kk < 32; kk++) {
            float4 wv = *(float4*)&sW[kk][lane * 4];
            #pragma unroll
            for (int r = 0; r < 8; r++) {
                float av = sA[wr * 8 + r][kk];
                acc[r][0] += av * wv.x;
                acc[r][1] += av * wv.y;
                acc[r][2] += av * wv.z;
                acc[r][3] += av * wv.w;
            }
        }
    }
    float4 a2v = *(const float4*)(a + OUT_F + lane * 4);
    #pragma unroll
    for (int r = 0; r < 8; r++) {
        int gr = r0 + wr * 8 + r;
        float t = acc[r][0] * a2v.x + acc[r][1] * a2v.y + acc[r][2] * a2v.z + acc[r][3] * a2v.w;
        #pragma unroll
        for (int o = 16; o > 0; o >>= 1) t += __shfl_xor_sync(0xffffffffu, t, o);
        if (gr < N_ATTRS) {
            *(float4*)&g_attr_h[(size_t)gr * OUT_F + lane * 4] =
                make_float4(acc[r][0], acc[r][1], acc[r][2], acc[r][3]);
            if (lane == 0) {
                g_Q[gr]  = expf(t);
                g_Qa[gr] = expf(LRELU_ALPHA * t);
            }
        }
    }
}

// ================= K3b: transpose + bf16 hi/lo split of attr_h =================
__global__ void k_trans(int dummy) {
    __shared__ float s[64][133];
    int tid = threadIdx.x;
    int j0 = blockIdx.x * JT;
    #pragma unroll
    for (int i = 0; i < 8; i++) {
        int id = tid + 256 * i;          // 2048 float4s
        int jr = id >> 5, f4 = id & 31;
        float4 v = make_float4(0.f, 0.f, 0.f, 0.f);
        if (j0 + jr < N_ATTRS)
            v = *(const float4*)&g_attr_h[(size_t)(j0 + jr) * OUT_F + f4 * 4];
        s[jr][f4 * 4 + 0] = v.x; s[jr][f4 * 4 + 1] = v.y;
        s[jr][f4 * 4 + 2] = v.z; s[jr][f4 * 4 + 3] = v.w;
    }
    __syncthreads();
    #pragma unroll
    for (int i = 0; i < 4; i++) {
        int id = tid + 256 * i;          // 1024 tasks: (f, 8-j chunk)
        int f = id >> 3, c = id & 7;
        u32 hw[4], lw[4];
        #pragma unroll
        for (int k = 0; k < 4; k++) {
            float v0 = s[c * 8 + 2 * k][f];
            float v1 = s[c * 8 + 2 * k + 1][f];
            u32 h = cvt_bf16x2(v0, v1);
            float h0 = __uint_as_float(h << 16);
            float h1 = __uint_as_float(h & 0xFFFF0000u);
            hw[k] = h;
            lw[k] = cvt_bf16x2(v0 - h0, v1 - h1);
        }
        size_t off = (size_t)f * VT_LD + j0 + c * 8;
        *(uint4*)&g_vt_hi[off] = make_uint4(hw[0], hw[1], hw[2], hw[3]);
        *(uint4*)&g_vt_lo[off] = make_uint4(lw[0], lw[1], lw[2], lw[3]);
    }
    if (blockIdx.x == NT_J - 1 && tid < VT_LD - N_ATTRS) {
        g_Q[N_ATTRS + tid] = 0.f;
        g_Qa[N_ATTRS + tid] = 0.f;
    }
}

// ================= K4: HMMA fused attention (split-j partials) =================
// CTA = 128 nodes x 128 feats x ~20 attr tiles. 8 warps; warp owns 16 node rows.
// A (weights, bf16 hi/lo) built directly in mma fragment layout from feat+P+Q.
// B (V^T hi/lo) staged in smem (144B pitch), ldmatrix.x4, double-buffered.
__global__ __launch_bounds__(256, 2) void k_mainT(const int* __restrict__ feat) {
    extern __shared__ char dsm[];
    const u32 smB = smem_u32(dsm);
    const int tid = threadIdx.x;
    const int wid = tid >> 5, lane = tid & 31;
    const int js = blockIdx.x & 3;
    const int n0 = (blockIdx.x >> 2) * M_TILE;
    const int t0 = js * TPS;
    const int NT = (NT_J - t0 < TPS) ? (NT_J - t0) : TPS;

    const int r0 = n0 + wid * 16 + (lane >> 2);
    const int r1 = r0 + 8;
    const int cq = (lane & 3) * 2;
    const bool v0 = r0 < N_NODES, v1 = r1 < N_NODES;
    const float P0  = v0 ? g_P[r0]  : 0.f;
    const float Pa0 = v0 ? g_Pa[r0] : 0.f;
    const float P1  = v1 ? g_P[r1]  : 0.f;
    const float Pa1 = v1 ? g_Pa[r1] : 0.f;
    const int* fr0 = feat + (size_t)r0 * N_ATTRS;
    const int* fr1 = feat + (size_t)r1 * N_ATTRS;

    float acc[16][4];
    #pragma unroll
    for (int i = 0; i < 16; i++)
        #pragma unroll
        for (int c = 0; c < 4; c++) acc[i][c] = 0.f;
    float den0 = 0.f, den1 = 0.f;

    // ldmatrix per-lane offset: lanes 0-7 rows+chunk0, 8-15 rows+chunk1,
    // 16-23 rows+8 chunk0, 24-31 rows+8 chunk1
    const u32 lmoff = (u32)(((lane & 7) + ((lane & 16) >> 1)) * VROW + ((lane & 8) >> 3) * 16);

    auto loadV = [&](int kt, int buf) {
        const int j0 = (t0 + kt) * JT;
        const u32 dst = smB + buf * (2 * VTILE);
        #pragma unroll
        for (int t = 0; t < 8; t++) {
            int id = tid + 256 * t;
            int f = (id >> 3) & 127, c = id & 7;
            const __nv_bfloat16* src = (t < 4) ? g_vt_hi : g_vt_lo;
            u32 d = dst + ((t < 4) ? 0u : (u32)VTILE) + (u32)(f * VROW + c * 16);
            cp_async16(d, src + (size_t)f * VT_LD + j0 + c * 8);
        }
        CP_COMMIT();
    };

    loadV(0, 0);
    for (int kt = 0; kt < NT; kt++) {
        const int b = kt & 1;
        if (kt + 1 < NT) {
            loadV(kt + 1, b ^ 1);
            asm volatile("cp.async.wait_group 1;" ::: "memory");
        } else {
            asm volatile("cp.async.wait_group 0;" ::: "memory");
        }
        __syncthreads();

        const u32 vh = smB + b * (2 * VTILE);
        const u32 vl = vh + VTILE;
        const int j0 = (t0 + kt) * JT;
        #pragma unroll
        for (int ks = 0; ks < 4; ks++) {
            const int c0 = j0 + ks * 16 + cq;
            const int c8 = c0 + 8;
            int2 m00 = make_int2(0, 0), m08 = m00, m10 = m00, m18 = m00;
            if (v0) {
                if (c0 < N_ATTRS) m00 = __ldg((const int2*)(fr0 + c0));
                if (c8 < N_ATTRS) m08 = __ldg((const int2*)(fr0 + c8));
            }
            if (v1) {
                if (c0 < N_ATTRS) m10 = __ldg((const int2*)(fr1 + c0));
                if (c8 < N_ATTRS) m18 = __ldg((const int2*)(fr1 + c8));
            }
            const float2 q0  = *(const float2*)&g_Q[c0];
            const float2 q8  = *(const float2*)&g_Q[c8];
            const float2 qa0 = *(const float2*)&g_Qa[c0];
            const float2 qa8 = *(const float2*)&g_Qa[c8];

            float w00 = wfun(m00.x, P0, Pa0, q0.x, qa0.x);
            float w01 = wfun(m00.y, P0, Pa0, q0.y, qa0.y);
            float w08 = wfun(m08.x, P0, Pa0, q8.x, qa8.x);
            float w09 = wfun(m08.y, P0, Pa0, q8.y, qa8.y);
            float w10 = wfun(m10.x, P1, Pa1, q0.x, qa0.x);
            float w11 = wfun(m10.y, P1, Pa1, q0.y, qa0.y);
            float w18 = wfun(m18.x, P1, Pa1, q8.x, qa8.x);
            float w19 = wfun(m18.y, P1, Pa1, q8.y, qa8.y);
            den0 += (w00 + w01) + (w08 + w09);
            den1 += (w10 + w11) + (w18 + w19);

            const u32 ah0 = cvt_bf16x2(w00, w01);
            const u32 ah1 = cvt_bf16x2(w10, w11);
            const u32 ah2 = cvt_bf16x2(w08, w09);
            const u32 ah3 = cvt_bf16x2(w18, w19);
            const u32 al0 = cvt_bf16x2(w00 - __uint_as_float(ah0 << 16),
                                       w01 - __uint_as_float(ah0 & 0xFFFF0000u));
            const u32 al1 = cvt_bf16x2(w10 - __uint_as_float(ah1 << 16),
                                       w11 - __uint_as_float(ah1 & 0xFFFF0000u));
            const u32 al2 = cvt_bf16x2(w08 - __uint_as_float(ah2 << 16),
                                       w09 - __uint_as_float(ah2 & 0xFFFF0000u));
            const u32 al3 = cvt_bf16x2(w18 - __uint_as_float(ah3 << 16),
                                       w19 - __uint_as_float(ah3 & 0xFFFF0000u));

            const u32 bh_base = vh + lmoff + ks * 32;
            const u32 bl_base = vl + lmoff + ks * 32;
            #pragma unroll
            for (int np = 0; np < 8; np++) {
                u32 bh0, bh1, bh2, bh3, bl0, bl1, bl2, bl3;
                LDSM4(bh0, bh1, bh2, bh3, bh_base + np * 16 * VROW);
                LDSM4(bl0, bl1, bl2, bl3, bl_base + np * 16 * VROW);
                mma16816(acc[2 * np],     ah0, ah1, ah2, ah3, bh0, bh1);
                mma16816(acc[2 * np + 1], ah0, ah1, ah2, ah3, bh2, bh3);
                mma16816(acc[2 * np],     ah0, ah1, ah2, ah3, bl0, bl1);
                mma16816(acc[2 * np + 1], ah0, ah1, ah2, ah3, bl2, bl3);
                mma16816(acc[2 * np],     al0, al1, al2, al3, bh0, bh1);
                mma16816(acc[2 * np + 1], al0, al1, al2, al3, bh2, bh3);
            }
        }
        __syncthreads();
    }

    // denominator partials: reduce across the 4 lanes sharing each row
    den0 += __shfl_xor_sync(0xffffffffu, den0, 1);
    den0 += __shfl_xor_sync(0xffffffffu, den0, 2);
    den1 += __shfl_xor_sync(0xffffffffu, den1, 1);
    den1 += __shfl_xor_sync(0xffffffffu, den1, 2);
    if ((lane & 3) == 0) {
        if (v0) g_den[js * N_NODES + r0] = den0;
        if (v1) g_den[js * N_NODES + r1] = den1;
    }

    // accumulator partials
    float* pb = g_part + (size_t)js * N_NODES * OUT_F;
    #pragma unroll
    for (int np = 0; np < 16; np++) {
        int col = np * 8 + cq;
        if (v0) *(float2*)(pb + (size_t)r0 * OUT_F + col) = make_float2(acc[np][0], acc[np][1]);
        if (v1) *(float2*)(pb + (size_t)r1 * OUT_F + col) = make_float2(acc[np][2], acc[np][3]);
    }
}

// ================= K5: reduce splits, normalize, ELU, store =================
__global__ void k_final(float* __restrict__ out) {
    int gid = blockIdx.x * blockDim.x + threadIdx.x;   // one float4 each
    int row = gid >> 5;
    int f = (gid & 31) * 4;
    if (row >= N_NODES) return;
    float4 s = make_float4(0.f, 0.f, 0.f, 0.f);
    float den = 0.f;
    #pragma unroll
    for (int sp = 0; sp < JSPLIT; sp++) {
        const float4 p = *(const float4*)(g_part + ((size_t)sp * N_NODES + row) * OUT_F + f);
        s.x += p.x; s.y += p.y; s.z += p.z; s.w += p.w;
        den += g_den[sp * N_NODES + row];
    }
    float inv = (den > 0.f) ? 1.f / den : 0.f;
    float o[4] = {s.x * inv, s.y * inv, s.z * inv, s.w * inv};
    #pragma unroll
    for (int e = 0; e < 4; e++) o[e] = (o[e] > 0.f) ? o[e] : expm1f(o[e]);
    *(float4*)(out + (size_t)row * OUT_F + f) = make_float4(o[0], o[1], o[2], o[3]);
}

extern "C" void kernel_launch(void* const* d_in, const int* in_sizes, int n_in,
                              void* d_out, int out_size) {
    const float* node_emb = (const float*)d_in[0];
    const float* attr_emb = (const float*)d_in[1];
    const int*   feat     = (const int*)d_in[2];
    const float* W        = (const float*)d_in[3];
    const float* a        = (const float*)d_in[4];
    float* out = (float*)d_out;

    cudaFuncSetAttribute(k_mainT, cudaFuncAttributeMaxDynamicSharedMemorySize, SMEM_BYTES);

    k_v1<<<(IN_F + 255) / 256, 256>>>(W, a);
    k_node<<<(N_NODES * 32 + 255) / 256, 256>>>(node_emb);
    k_attr<<<(N_ATTRS + 63) / 64, 256>>>(attr_emb, W, a);
    k_trans<<<NT_J, 256>>>(0);
    k_mainT<<<N_CTAS_N * JSPLIT, 256, SMEM_BYTES>>>(feat);
    k_final<<<(N_NODES * 32 + 255) / 256, 256>>>(out);
}

// round 6
// speedup vs baseline: 5.1868x; 2.0793x over previous
#include <cuda_runtime.h>
#include <cuda_fp16.h>
#include <cstdint>

#define N_NODES 20000
#define N_ATTRS 5000
#define IN_F 512
#define OUT_F 128
#define LRELU_ALPHA 0.2f

#define M_TILE 128
#define JT 64
#define VT_LD 5056           // padded attr count (79*64)
#define NT_J 79              // total 64-attr tiles
#define JSPLIT 4
#define TPS 20               // tiles per split (last split gets 19)
#define N_CTAS_N 157         // ceil(20000/128)
#define VROW 144             // smem V row pitch (bytes): conflict-free ldmatrix
#define VTILE (128 * VROW)   // 18432 B per fp16 tile
#define SQ_OFF (2 * VTILE)          // 36864
#define SQA_OFF (SQ_OFF + TPS * JT * 4)   // 41984
#define SMEM_BYTES (SQA_OFF + TPS * JT * 4)  // 47104

typedef unsigned long long ull;
typedef unsigned int u32;

// ---------------- scratch (no cudaMalloc allowed) ----------------
__device__ __align__(16) float g_v1[IN_F];
__device__ __align__(16) float g_P[N_NODES];     // scaled exp(s)
__device__ __align__(16) float g_Pa[N_NODES];    // scaled exp(alpha*s)
__device__ __align__(16) float g_sc[N_NODES];    // per-node scale
__device__ __align__(16) float g_Q[VT_LD];
__device__ __align__(16) float g_Qa[VT_LD];
__device__ __align__(16) __half g_vt[(size_t)OUT_F * VT_LD];   // V^T fp16
__device__ __align__(16) float g_part[(size_t)JSPLIT * N_NODES * OUT_F];
__device__ __align__(16) float g_den[JSPLIT * N_NODES];
__device__ int g_qmax_i;

// ---------------- helpers ----------------
__device__ __forceinline__ u32 smem_u32(const void* p) {
    u32 a;
    asm("{ .reg .u64 t; cvta.to.shared.u64 t, %1; cvt.u32.u64 %0, t; }" : "=r"(a) : "l"(p));
    return a;
}
__device__ __forceinline__ void cp_async16(u32 smem, const void* gmem) {
    asm volatile("cp.async.cg.shared.global [%0], [%1], 16;" :: "r"(smem), "l"(gmem));
}
#define CP_COMMIT() asm volatile("cp.async.commit_group;")

__device__ __forceinline__ u32 cvt_f16x2(float lo, float hi) {
    u32 r;
    asm("cvt.rn.f16x2.f32 %0, %1, %2;" : "=r"(r) : "f"(hi), "f"(lo));
    return r;
}
#define LDSM4(r0, r1, r2, r3, addr) \
    asm volatile("ldmatrix.sync.aligned.m8n8.x4.shared.b16 {%0,%1,%2,%3}, [%4];" \
        : "=r"(r0), "=r"(r1), "=r"(r2), "=r"(r3) : "r"(addr))

__device__ __forceinline__ void mma16816(float* c, u32 a0, u32 a1, u32 a2, u32 a3,
                                         u32 b0, u32 b1) {
    asm volatile("mma.sync.aligned.m16n8k16.row.col.f32.f16.f16.f32 "
        "{%0,%1,%2,%3}, {%4,%5,%6,%7}, {%8,%9}, {%0,%1,%2,%3};"
        : "+f"(c[0]), "+f"(c[1]), "+f"(c[2]), "+f"(c[3])
        : "r"(a0), "r"(a1), "r"(a2), "r"(a3), "r"(b0), "r"(b1));
}
// scaled weight: w' = m * ( P'q >= sc ? P'q : Pa'qa )
__device__ __forceinline__ float wfun(int m, float P, float Pa, float sc, float q, float qa) {
    float pq = P * q;
    float w = (pq >= sc) ? pq : Pa * qa;
    return (m > 0) ? w : 0.f;
}

// ================= K0: v1 = W @ a1 ; zero pads; reset qmax =================
__global__ void k_v1(const float* __restrict__ W, const float* __restrict__ a) {
    __shared__ float sa[OUT_F];
    if (threadIdx.x < OUT_F) sa[threadIdx.x] = a[threadIdx.x];
    __syncthreads();
    int k = blockIdx.x * blockDim.x + threadIdx.x;
    if (k < IN_F) {
        const float* wr = W + (size_t)k * OUT_F;
        float s = 0.f;
        #pragma unroll 16
        for (int f = 0; f < OUT_F; f++) s += wr[f] * sa[f];
        g_v1[k] = s;
    }
    if (blockIdx.x == 0) {
        int tid = threadIdx.x;
        if (tid == 0) g_qmax_i = 0;
        if (tid < VT_LD - N_ATTRS) {        // 56
            g_Q[N_ATTRS + tid] = 0.f;
            g_Qa[N_ATTRS + tid] = 0.f;
        }
        // zero g_vt pad columns j in [5000, 5056) for all 128 f-rows
        u32* vt32 = (u32*)g_vt;
        for (int idx = tid; idx < 128 * 28; idx += 256) {
            int f = idx / 28, c = idx % 28;
            vt32[((size_t)f * VT_LD + N_ATTRS) / 2 + c] = 0u;
        }
    }
}

// ================= K1: attr_h = attr_emb @ W ; Q,Qa ; V^T fp16 ; qmax =====
__global__ void k_attr(const float* __restrict__ ae, const float* __restrict__ Wm,
                       const float* __restrict__ a) {
    __shared__ float sA[64][32];
    __shared__ float sW[32][OUT_F];
    int tid = threadIdx.x;
    int r0 = blockIdx.x * 64;
    int wr = tid >> 5;
    int lane = tid & 31;
    float acc[8][4];
    #pragma unroll
    for (int i = 0; i < 8; i++)
        #pragma unroll
        for (int c = 0; c < 4; c++) acc[i][c] = 0.f;

    for (int k0 = 0; k0 < IN_F; k0 += 32) {
        __syncthreads();
        #pragma unroll
        for (int it = 0; it < 8; it++) {
            int idx = tid + 256 * it;
            int r = idx >> 5, kk = idx & 31;
            int gr = r0 + r;
            sA[r][kk] = (gr < N_ATTRS) ? ae[(size_t)gr * IN_F + k0 + kk] : 0.f;
        }
        #pragma unroll
        for (int it = 0; it < 4; it++) {
            int idx = tid + 256 * it;
            int kk = idx >> 5, f4 = idx & 31;
            *(float4*)&sW[kk][f4 * 4] = *(const float4*)(Wm + (size_t)(k0 + kk) * OUT_F + f4 * 4);
        }
        __syncthreads();
        #pragma unroll 8
        for (int kk = 0; kk < 32; kk++) {
            float4 wv = *(float4*)&sW[kk][lane * 4];
            #pragma unroll
            for (int r = 0; r < 8; r++) {
                float av = sA[wr * 8 + r][kk];
                acc[r][0] += av * wv.x;
                acc[r][1] += av * wv.y;
                acc[r][2] += av * wv.z;
                acc[r][3] += av * wv.w;
            }
        }
    }
    // V^T fp16: thread owns cols f = lane*4..+3, rows j = r0+wr*8 .. +7
    #pragma unroll
    for (int c = 0; c < 4; c++) {
        u32 p[4];
        #pragma unroll
        for (int k = 0; k < 4; k++)
            p[k] = cvt_f16x2(acc[2 * k][c], acc[2 * k + 1][c]);
        int jbase = r0 + wr * 8;
        if (jbase < N_ATTRS) {   // r0 tiles of 64 fit; N_ATTRS multiple of 8
            size_t off = (size_t)(lane * 4 + c) * VT_LD + jbase;
            *(uint4*)&g_vt[off] = make_uint4(p[0], p[1], p[2], p[3]);
        }
    }
    // scores
    float4 a2v = *(const float4*)(a + OUT_F + lane * 4);
    float qmax = 0.f;
    #pragma unroll
    for (int r = 0; r < 8; r++) {
        int gr = r0 + wr * 8 + r;
        float t = acc[r][0] * a2v.x + acc[r][1] * a2v.y + acc[r][2] * a2v.z + acc[r][3] * a2v.w;
        #pragma unroll
        for (int o = 16; o > 0; o >>= 1) t += __shfl_xor_sync(0xffffffffu, t, o);
        if (gr < N_ATTRS) {
            float Q = expf(t);
            if (lane == 0) {
                g_Q[gr]  = Q;
                g_Qa[gr] = expf(LRELU_ALPHA * t);
            }
            if (Q > qmax) qmax = Q;
        }
    }
    if (lane == 0) atomicMax(&g_qmax_i, __float_as_int(qmax));
}

// ================= K2: node scores -> scaled P, Pa, sc =================
__global__ void k_node(const float* __restrict__ ne) {
    int gw = (blockIdx.x * blockDim.x + threadIdx.x) >> 5;
    int lane = threadIdx.x & 31;
    if (gw >= N_NODES) return;
    const float4* row = (const float4*)(ne + (size_t)gw * IN_F);
    const float4* v1 = (const float4*)g_v1;
    float s = 0.f;
    #pragma unroll
    for (int t = 0; t < 4; t++) {
        float4 x = row[lane + 32 * t];
        float4 c = v1[lane + 32 * t];
        s += x.x * c.x + x.y * c.y + x.z * c.z + x.w * c.w;
    }
    #pragma unroll
    for (int o = 16; o > 0; o >>= 1) s += __shfl_xor_sync(0xffffffffu, s, o);
    if (lane == 0) {
        float P  = expf(s);
        float Pa = expf(LRELU_ALPHA * s);
        float Qmax = __int_as_float(g_qmax_i);
        float wmax = P * Qmax;
        if (wmax < 1.f) wmax = 1.f;
        float sc = 1.f / wmax;
        g_P[gw]  = P * sc;
        g_Pa[gw] = Pa * sc;
        g_sc[gw] = sc;
    }
}

// ================= K3: fp16 HMMA fused attention (split-j partials) =========
// CTA = 128 nodes x 128 feats x <=20 contiguous 64-attr tiles. 8 warps.
// A (scaled weights fp16) built in-register in mma fragment layout; feat
// prefetched one k-slice ahead. B (V^T fp16) cp.async double-buffered.
__global__ __launch_bounds__(256, 2) void k_mainT(const int* __restrict__ feat) {
    extern __shared__ char dsm[];
    const u32 smB = smem_u32(dsm);
    float* sQ  = (float*)(dsm + SQ_OFF);
    float* sQa = (float*)(dsm + SQA_OFF);
    const int tid = threadIdx.x;
    const int wid = tid >> 5, lane = tid & 31;
    const int js = blockIdx.x & 3;
    const int n0 = (blockIdx.x >> 2) * M_TILE;
    const int t0 = js * TPS;
    const int NT = (NT_J - t0 < TPS) ? (NT_J - t0) : TPS;
    const int jg0 = t0 * JT;                 // contiguous split base

    // stage Q/Qa for this split
    for (int idx = tid; idx < NT * JT; idx += 256) {
        sQ[idx]  = g_Q[jg0 + idx];
        sQa[idx] = g_Qa[jg0 + idx];
    }

    const int r0 = n0 + wid * 16 + (lane >> 2);
    const int r1 = r0 + 8;
    const int cq = (lane & 3) * 2;
    const bool v0 = r0 < N_NODES, v1 = r1 < N_NODES;
    const float P0  = v0 ? g_P[r0]  : 0.f;
    const float Pa0 = v0 ? g_Pa[r0] : 0.f;
    const float s0  = v0 ? g_sc[r0] : 1.f;
    const float P1  = v1 ? g_P[r1]  : 0.f;
    const float Pa1 = v1 ? g_Pa[r1] : 0.f;
    const float s1  = v1 ? g_sc[r1] : 1.f;
    const int* fr0 = feat + (size_t)r0 * N_ATTRS;
    const int* fr1 = feat + (size_t)r1 * N_ATTRS;

    float acc[16][4];
    #pragma unroll
    for (int i = 0; i < 16; i++)
        #pragma unroll
        for (int c = 0; c < 4; c++) acc[i][c] = 0.f;
    float den0 = 0.f, den1 = 0.f;

    const u32 lmoff = (u32)(((lane & 7) + ((lane & 16) >> 1)) * VROW + ((lane & 8) >> 3) * 16);

    auto loadV = [&](int kt, int buf) {
        const int j0 = jg0 + kt * JT;
        const u32 dst = smB + buf * VTILE;
        #pragma unroll
        for (int t = 0; t < 4; t++) {
            int id = tid + 256 * t;          // 1024 chunks of 16B
            int f = id >> 3, c = id & 7;
            cp_async16(dst + (u32)(f * VROW + c * 16),
                       g_vt + (size_t)f * VT_LD + j0 + c * 8);
        }
        CP_COMMIT();
    };
    // prefetch regs for one k-slice: 4 x int2 (rows r0,r1 at cols c0, c0+8)
    int2 pm[4];
    auto prefetchF = [&](int kt, int ks) {
        const int c0 = jg0 + kt * JT + ks * 16 + cq;
        const int c8 = c0 + 8;
        pm[0] = (v0 && c0 < N_ATTRS) ? __ldg((const int2*)(fr0 + c0)) : make_int2(0, 0);
        pm[1] = (v0 && c8 < N_ATTRS) ? __ldg((const int2*)(fr0 + c8)) : make_int2(0, 0);
        pm[2] = (v1 && c0 < N_ATTRS) ? __ldg((const int2*)(fr1 + c0)) : make_int2(0, 0);
        pm[3] = (v1 && c8 < N_ATTRS) ? __ldg((const int2*)(fr1 + c8)) : make_int2(0, 0);
    };

    loadV(0, 0);
    prefetchF(0, 0);
    __syncthreads();   // sQ ready

    for (int kt = 0; kt < NT; kt++) {
        const int b = kt & 1;
        if (kt + 1 < NT) {
            loadV(kt + 1, b ^ 1);
            asm volatile("cp.async.wait_group 1;" ::: "memory");
        } else {
            asm volatile("cp.async.wait_group 0;" ::: "memory");
        }
        __syncthreads();

        const u32 vb = smB + b * VTILE;
        #pragma unroll
        for (int ks = 0; ks < 4; ks++) {
            const int2 m00 = pm[0], m08 = pm[1], m10 = pm[2], m18 = pm[3];
            if (ks < 3) prefetchF(kt, ks + 1);
            else if (kt + 1 < NT) prefetchF(kt + 1, 0);

            const int jl = kt * JT + ks * 16 + cq;  // local index into sQ
            const float2 q0  = *(const float2*)&sQ[jl];
            const float2 q8  = *(const float2*)&sQ[jl + 8];
            const float2 qa0 = *(const float2*)&sQa[jl];
            const float2 qa8 = *(const float2*)&sQa[jl + 8];

            float w00 = wfun(m00.x, P0, Pa0, s0, q0.x, qa0.x);
            float w01 = wfun(m00.y, P0, Pa0, s0, q0.y, qa0.y);
            float w08 = wfun(m08.x, P0, Pa0, s0, q8.x, qa8.x);
            float w09 = wfun(m08.y, P0, Pa0, s0, q8.y, qa8.y);
            float w10 = wfun(m10.x, P1, Pa1, s1, q0.x, qa0.x);
            float w11 = wfun(m10.y, P1, Pa1, s1, q0.y, qa0.y);
            float w18 = wfun(m18.x, P1, Pa1, s1, q8.x, qa8.x);
            float w19 = wfun(m18.y, P1, Pa1, s1, q8.y, qa8.y);
            den0 += (w00 + w01) + (w08 + w09);
            den1 += (w10 + w11) + (w18 + w19);

            const u32 a0 = cvt_f16x2(w00, w01);
            const u32 a1 = cvt_f16x2(w10, w11);
            const u32 a2 = cvt_f16x2(w08, w09);
            const u32 a3 = cvt_f16x2(w18, w19);

            const u32 bbase = vb + lmoff + ks * 32;
            #pragma unroll
            for (int np = 0; np < 8; np++) {
                u32 b0, b1, b2, b3;
                LDSM4(b0, b1, b2, b3, bbase + np * 16 * VROW);
                mma16816(acc[2 * np],     a0, a1, a2, a3, b0, b1);
                mma16816(acc[2 * np + 1], a0, a1, a2, a3, b2, b3);
            }
        }
        __syncthreads();
    }

    // denominator partials (4 lanes share each row)
    den0 += __shfl_xor_sync(0xffffffffu, den0, 1);
    den0 += __shfl_xor_sync(0xffffffffu, den0, 2);
    den1 += __shfl_xor_sync(0xffffffffu, den1, 1);
    den1 += __shfl_xor_sync(0xffffffffu, den1, 2);
    if ((lane & 3) == 0) {
        if (v0) g_den[js * N_NODES + r0] = den0;
        if (v1) g_den[js * N_NODES + r1] = den1;
    }
    // accumulator partials
    float* pb = g_part + (size_t)js * N_NODES * OUT_F;
    #pragma unroll
    for (int np = 0; np < 16; np++) {
        int col = np * 8 + cq;
        if (v0) *(float2*)(pb + (size_t)r0 * OUT_F + col) = make_float2(acc[np][0], acc[np][1]);
        if (v1) *(float2*)(pb + (size_t)r1 * OUT_F + col) = make_float2(acc[np][2], acc[np][3]);
    }
}

// ================= K4: reduce splits, normalize, ELU, store =================
__global__ void k_final(float* __restrict__ out) {
    int gid = blockIdx.x * blockDim.x + threadIdx.x;   // one float4 each
    int row = gid >> 5;
    int f = (gid & 31) * 4;
    if (row >= N_NODES) return;
    float4 s = make_float4(0.f, 0.f, 0.f, 0.f);
    float den = 0.f;
    #pragma unroll
    for (int sp = 0; sp < JSPLIT; sp++) {
        const float4 p = *(const float4*)(g_part + ((size_t)sp * N_NODES + row) * OUT_F + f);
        s.x += p.x; s.y += p.y; s.z += p.z; s.w += p.w;
        den += g_den[sp * N_NODES + row];
    }
    float inv = (den > 0.f) ? 1.f / den : 0.f;
    float o[4] = {s.x * inv, s.y * inv, s.z * inv, s.w * inv};
    #pragma unroll
    for (int e = 0; e < 4; e++) o[e] = (o[e] > 0.f) ? o[e] : expm1f(o[e]);
    *(float4*)(out + (size_t)row * OUT_F + f) = make_float4(o[0], o[1], o[2], o[3]);
}

extern "C" void kernel_launch(void* const* d_in, const int* in_sizes, int n_in,
                              void* d_out, int out_size) {
    const float* node_emb = (const float*)d_in[0];
    const float* attr_emb = (const float*)d_in[1];
    const int*   feat     = (const int*)d_in[2];
    const float* W        = (const float*)d_in[3];
    const float* a        = (const float*)d_in[4];
    float* out = (float*)d_out;

    cudaFuncSetAttribute(k_mainT, cudaFuncAttributeMaxDynamicSharedMemorySize, SMEM_BYTES);

    k_v1<<<(IN_F + 255) / 256, 256>>>(W, a);                 // idx 0
    k_attr<<<(N_ATTRS + 63) / 64, 256>>>(attr_emb, W, a);    // idx 1
    k_node<<<(N_NODES * 32 + 255) / 256, 256>>>(node_emb);   // idx 2
    k_mainT<<<N_CTAS_N * JSPLIT, 256, SMEM_BYTES>>>(feat);   // idx 3 (profiled)
    k_final<<<(N_NODES * 32 + 255) / 256, 256>>>(out);       // idx 4
}

// round 7
// speedup vs baseline: 5.6023x; 1.0801x over previous
#include <cuda_runtime.h>
#include <cuda_fp16.h>
#include <cstdint>

#define N_NODES 20000
#define N_ATTRS 5000
#define IN_F 512
#define OUT_F 128
#define LRELU_ALPHA 0.2f

#define M_TILE 128
#define JT 64
#define VT_LD 5056           // padded attr count (79*64)
#define NT_J 79              // total 64-attr tiles
#define JSPLIT 4
#define TPS 20               // tiles per split (last split gets 19)
#define N_CTAS_N 157         // ceil(20000/128)
#define VROW 144             // smem V row pitch (bytes): conflict-free ldmatrix
#define VTILE (128 * VROW)   // 18432 B per fp16 tile
#define NBUF 3
#define SQ_OFF (NBUF * VTILE)             // 55296
#define SQA_OFF (SQ_OFF + TPS * JT * 4)   // 60416
#define SMEM_BYTES (SQA_OFF + TPS * JT * 4)  // 65536

typedef unsigned long long ull;
typedef unsigned int u32;

// ---------------- scratch (no cudaMalloc allowed) ----------------
__device__ __align__(16) float g_v1[IN_F];
__device__ __align__(16) float g_P[N_NODES];     // scaled exp(s)
__device__ __align__(16) float g_Pa[N_NODES];    // scaled exp(alpha*s)
__device__ __align__(16) float g_sc[N_NODES];    // per-node scale
__device__ __align__(16) float g_Q[VT_LD];
__device__ __align__(16) float g_Qa[VT_LD];
__device__ __align__(16) __half g_vt[(size_t)OUT_F * VT_LD];   // V^T fp16
__device__ __align__(16) float g_part[(size_t)JSPLIT * N_NODES * OUT_F];
__device__ __align__(16) float g_den[JSPLIT * N_NODES];
__device__ int g_qmax_i;

// ---------------- helpers ----------------
__device__ __forceinline__ u32 smem_u32(const void* p) {
    u32 a;
    asm("{ .reg .u64 t; cvta.to.shared.u64 t, %1; cvt.u32.u64 %0, t; }" : "=r"(a) : "l"(p));
    return a;
}
__device__ __forceinline__ void cp_async16(u32 smem, const void* gmem) {
    asm volatile("cp.async.cg.shared.global [%0], [%1], 16;" :: "r"(smem), "l"(gmem));
}
#define CP_COMMIT() asm volatile("cp.async.commit_group;")

__device__ __forceinline__ u32 cvt_f16x2(float lo, float hi) {
    u32 r;
    asm("cvt.rn.f16x2.f32 %0, %1, %2;" : "=r"(r) : "f"(hi), "f"(lo));
    return r;
}
#define LDSM4(r0, r1, r2, r3, addr) \
    asm volatile("ldmatrix.sync.aligned.m8n8.x4.shared.b16 {%0,%1,%2,%3}, [%4];" \
        : "=r"(r0), "=r"(r1), "=r"(r2), "=r"(r3) : "r"(addr))

__device__ __forceinline__ void mma16816(float* c, u32 a0, u32 a1, u32 a2, u32 a3,
                                         u32 b0, u32 b1) {
    asm volatile("mma.sync.aligned.m16n8k16.row.col.f32.f16.f16.f32 "
        "{%0,%1,%2,%3}, {%4,%5,%6,%7}, {%8,%9}, {%0,%1,%2,%3};"
        : "+f"(c[0]), "+f"(c[1]), "+f"(c[2]), "+f"(c[3])
        : "r"(a0), "r"(a1), "r"(a2), "r"(a3), "r"(b0), "r"(b1));
}
// scaled weight: w' = m * ( P'q >= sc ? P'q : Pa'qa )
__device__ __forceinline__ float wfun(int m, float P, float Pa, float sc, float q, float qa) {
    float pq = P * q;
    float w = (pq >= sc) ? pq : Pa * qa;
    return (m > 0) ? w : 0.f;
}

// ================= K0: v1 = W @ a1 ; zero pads; reset qmax =================
__global__ void k_v1(const float* __restrict__ W, const float* __restrict__ a) {
    __shared__ float sa[OUT_F];
    if (threadIdx.x < OUT_F) sa[threadIdx.x] = a[threadIdx.x];
    __syncthreads();
    int k = blockIdx.x * blockDim.x + threadIdx.x;
    if (k < IN_F) {
        const float* wr = W + (size_t)k * OUT_F;
        float s = 0.f;
        #pragma unroll 16
        for (int f = 0; f < OUT_F; f++) s += wr[f] * sa[f];
        g_v1[k] = s;
    }
    if (blockIdx.x == 0) {
        int tid = threadIdx.x;
        if (tid == 0) g_qmax_i = 0;
        if (tid < VT_LD - N_ATTRS) {        // 56
            g_Q[N_ATTRS + tid] = 0.f;
            g_Qa[N_ATTRS + tid] = 0.f;
        }
        // zero g_vt pad columns j in [5000, 5056) for all 128 f-rows
        u32* vt32 = (u32*)g_vt;
        for (int idx = tid; idx < 128 * 28; idx += 256) {
            int f = idx / 28, c = idx % 28;
            vt32[((size_t)f * VT_LD + N_ATTRS) / 2 + c] = 0u;
        }
    }
}

// ================= K1: attr_h = attr_emb @ W ; Q,Qa ; V^T fp16 ; qmax =====
__global__ void k_attr(const float* __restrict__ ae, const float* __restrict__ Wm,
                       const float* __restrict__ a) {
    __shared__ float sA[64][32];
    __shared__ float sW[32][OUT_F];
    int tid = threadIdx.x;
    int r0 = blockIdx.x * 64;
    int wr = tid >> 5;
    int lane = tid & 31;
    float acc[8][4];
    #pragma unroll
    for (int i = 0; i < 8; i++)
        #pragma unroll
        for (int c = 0; c < 4; c++) acc[i][c] = 0.f;

    for (int k0 = 0; k0 < IN_F; k0 += 32) {
        __syncthreads();
        #pragma unroll
        for (int it = 0; it < 8; it++) {
            int idx = tid + 256 * it;
            int r = idx >> 5, kk = idx & 31;
            int gr = r0 + r;
            sA[r][kk] = (gr < N_ATTRS) ? ae[(size_t)gr * IN_F + k0 + kk] : 0.f;
        }
        #pragma unroll
        for (int it = 0; it < 4; it++) {
            int idx = tid + 256 * it;
            int kk = idx >> 5, f4 = idx & 31;
            *(float4*)&sW[kk][f4 * 4] = *(const float4*)(Wm + (size_t)(k0 + kk) * OUT_F + f4 * 4);
        }
        __syncthreads();
        #pragma unroll 8
        for (int kk = 0; kk < 32; kk++) {
            float4 wv = *(float4*)&sW[kk][lane * 4];
            #pragma unroll
            for (int r = 0; r < 8; r++) {
                float av = sA[wr * 8 + r][kk];
                acc[r][0] += av * wv.x;
                acc[r][1] += av * wv.y;
                acc[r][2] += av * wv.z;
                acc[r][3] += av * wv.w;
            }
        }
    }
    // V^T fp16: thread owns cols f = lane*4..+3, rows j = r0+wr*8 .. +7
    #pragma unroll
    for (int c = 0; c < 4; c++) {
        u32 p[4];
        #pragma unroll
        for (int k = 0; k < 4; k++)
            p[k] = cvt_f16x2(acc[2 * k][c], acc[2 * k + 1][c]);
        int jbase = r0 + wr * 8;
        if (jbase < N_ATTRS) {
            size_t off = (size_t)(lane * 4 + c) * VT_LD + jbase;
            *(uint4*)&g_vt[off] = make_uint4(p[0], p[1], p[2], p[3]);
        }
    }
    // scores
    float4 a2v = *(const float4*)(a + OUT_F + lane * 4);
    float qmax = 0.f;
    #pragma unroll
    for (int r = 0; r < 8; r++) {
        int gr = r0 + wr * 8 + r;
        float t = acc[r][0] * a2v.x + acc[r][1] * a2v.y + acc[r][2] * a2v.z + acc[r][3] * a2v.w;
        #pragma unroll
        for (int o = 16; o > 0; o >>= 1) t += __shfl_xor_sync(0xffffffffu, t, o);
        if (gr < N_ATTRS) {
            float Q = expf(t);
            if (lane == 0) {
                g_Q[gr]  = Q;
                g_Qa[gr] = expf(LRELU_ALPHA * t);
            }
            if (Q > qmax) qmax = Q;
        }
    }
    if (lane == 0) atomicMax(&g_qmax_i, __float_as_int(qmax));
}

// ================= K2: node scores -> scaled P, Pa, sc =================
__global__ void k_node(const float* __restrict__ ne) {
    int gw = (blockIdx.x * blockDim.x + threadIdx.x) >> 5;
    int lane = threadIdx.x & 31;
    if (gw >= N_NODES) return;
    const float4* row = (const float4*)(ne + (size_t)gw * IN_F);
    const float4* v1 = (const float4*)g_v1;
    float s = 0.f;
    #pragma unroll
    for (int t = 0; t < 4; t++) {
        float4 x = row[lane + 32 * t];
        float4 c = v1[lane + 32 * t];
        s += x.x * c.x + x.y * c.y + x.z * c.z + x.w * c.w;
    }
    #pragma unroll
    for (int o = 16; o > 0; o >>= 1) s += __shfl_xor_sync(0xffffffffu, s, o);
    if (lane == 0) {
        float P  = expf(s);
        float Pa = expf(LRELU_ALPHA * s);
        float Qmax = __int_as_float(g_qmax_i);
        float wmax = P * Qmax;
        if (wmax < 1.f) wmax = 1.f;
        float sc = 1.f / wmax;
        g_P[gw]  = P * sc;
        g_Pa[gw] = Pa * sc;
        g_sc[gw] = sc;
    }
}

// ================= K3: fp16 HMMA fused attention (split-j partials) =========
// CTA = 128 nodes x 128 feats x <=20 contiguous 64-attr tiles. 8 warps.
// 3-stage cp.async V pipeline (1 barrier/tile); feat prefetch distance 2.
__global__ __launch_bounds__(256, 2) void k_mainT(const int* __restrict__ feat) {
    extern __shared__ char dsm[];
    const u32 smB = smem_u32(dsm);
    float* sQ  = (float*)(dsm + SQ_OFF);
    float* sQa = (float*)(dsm + SQA_OFF);
    const int tid = threadIdx.x;
    const int wid = tid >> 5, lane = tid & 31;
    const int js = blockIdx.x & 3;
    const int n0 = (blockIdx.x >> 2) * M_TILE;
    const int t0 = js * TPS;
    const int NT = (NT_J - t0 < TPS) ? (NT_J - t0) : TPS;
    const int NS = NT * 4;                  // total k-slices
    const int jg0 = t0 * JT;                // contiguous split base

    // stage Q/Qa for this split
    for (int idx = tid; idx < NT * JT; idx += 256) {
        sQ[idx]  = g_Q[jg0 + idx];
        sQa[idx] = g_Qa[jg0 + idx];
    }

    const int r0 = n0 + wid * 16 + (lane >> 2);
    const int r1 = r0 + 8;
    const int cq = (lane & 3) * 2;
    const bool v0 = r0 < N_NODES, v1 = r1 < N_NODES;
    const float P0  = v0 ? g_P[r0]  : 0.f;
    const float Pa0 = v0 ? g_Pa[r0] : 0.f;
    const float s0  = v0 ? g_sc[r0] : 1.f;
    const float P1  = v1 ? g_P[r1]  : 0.f;
    const float Pa1 = v1 ? g_Pa[r1] : 0.f;
    const float s1  = v1 ? g_sc[r1] : 1.f;
    const int* fr0 = feat + (size_t)r0 * N_ATTRS;
    const int* fr1 = feat + (size_t)r1 * N_ATTRS;

    float acc[16][4];
    #pragma unroll
    for (int i = 0; i < 16; i++)
        #pragma unroll
        for (int c = 0; c < 4; c++) acc[i][c] = 0.f;
    float den0 = 0.f, den1 = 0.f;

    const u32 lmoff = (u32)(((lane & 7) + ((lane & 16) >> 1)) * VROW + ((lane & 8) >> 3) * 16);

    auto loadV = [&](int kt) {
        const int j0 = jg0 + kt * JT;
        const u32 dst = smB + (kt % NBUF) * VTILE;
        #pragma unroll
        for (int t = 0; t < 4; t++) {
            int id = tid + 256 * t;          // 1024 chunks of 16B
            int f = id >> 3, c = id & 7;
            cp_async16(dst + (u32)(f * VROW + c * 16),
                       g_vt + (size_t)f * VT_LD + j0 + c * 8);
        }
        CP_COMMIT();
    };
    // feat prefetch for slice s (16 attrs starting at jg0 + s*16)
    auto prefetchF = [&](int s, int2* pm) {
        const int c0 = jg0 + s * 16 + cq;
        const int c8 = c0 + 8;
        bool in = s < NS;
        pm[0] = (in && v0 && c0 < N_ATTRS) ? __ldg((const int2*)(fr0 + c0)) : make_int2(0, 0);
        pm[1] = (in && v0 && c8 < N_ATTRS) ? __ldg((const int2*)(fr0 + c8)) : make_int2(0, 0);
        pm[2] = (in && v1 && c0 < N_ATTRS) ? __ldg((const int2*)(fr1 + c0)) : make_int2(0, 0);
        pm[3] = (in && v1 && c8 < N_ATTRS) ? __ldg((const int2*)(fr1 + c8)) : make_int2(0, 0);
    };

    int2 pmA[4], pmB[4];
    loadV(0);
    if (NT > 1) loadV(1);
    prefetchF(0, pmA);
    prefetchF(1, pmB);

    for (int kt = 0; kt < NT; kt++) {
        // tile kt's V buffer complete; at most 1 group (kt+1) pending
        asm volatile("cp.async.wait_group 1;" ::: "memory");
        __syncthreads();                 // single barrier per tile
        if (kt + 2 < NT) loadV(kt + 2);  // overwrites buf read at kt-1: safe post-barrier

        const u32 vb = smB + (kt % NBUF) * VTILE;
        #pragma unroll
        for (int ks = 0; ks < 4; ks++) {
            const int2 m00 = pmA[0], m08 = pmA[1], m10 = pmA[2], m18 = pmA[3];
            #pragma unroll
            for (int i = 0; i < 4; i++) pmA[i] = pmB[i];
            prefetchF(kt * 4 + ks + 2, pmB);   // distance-2 prefetch

            const int jl = kt * JT + ks * 16 + cq;  // local index into sQ
            const float2 q0  = *(const float2*)&sQ[jl];
            const float2 q8  = *(const float2*)&sQ[jl + 8];
            const float2 qa0 = *(const float2*)&sQa[jl];
            const float2 qa8 = *(const float2*)&sQa[jl + 8];

            float w00 = wfun(m00.x, P0, Pa0, s0, q0.x, qa0.x);
            float w01 = wfun(m00.y, P0, Pa0, s0, q0.y, qa0.y);
            float w08 = wfun(m08.x, P0, Pa0, s0, q8.x, qa8.x);
            float w09 = wfun(m08.y, P0, Pa0, s0, q8.y, qa8.y);
            float w10 = wfun(m10.x, P1, Pa1, s1, q0.x, qa0.x);
            float w11 = wfun(m10.y, P1, Pa1, s1, q0.y, qa0.y);
            float w18 = wfun(m18.x, P1, Pa1, s1, q8.x, qa8.x);
            float w19 = wfun(m18.y, P1, Pa1, s1, q8.y, qa8.y);
            den0 += (w00 + w01) + (w08 + w09);
            den1 += (w10 + w11) + (w18 + w19);

            const u32 a0 = cvt_f16x2(w00, w01);
            const u32 a1 = cvt_f16x2(w10, w11);
            const u32 a2 = cvt_f16x2(w08, w09);
            const u32 a3 = cvt_f16x2(w18, w19);

            const u32 bbase = vb + lmoff + ks * 32;
            #pragma unroll
            for (int np = 0; np < 8; np++) {
                u32 b0, b1, b2, b3;
                LDSM4(b0, b1, b2, b3, bbase + np * 16 * VROW);
                mma16816(acc[2 * np],     a0, a1, a2, a3, b0, b1);
                mma16816(acc[2 * np + 1], a0, a1, a2, a3, b2, b3);
            }
        }
    }

    // denominator partials (4 lanes share each row)
    den0 += __shfl_xor_sync(0xffffffffu, den0, 1);
    den0 += __shfl_xor_sync(0xffffffffu, den0, 2);
    den1 += __shfl_xor_sync(0xffffffffu, den1, 1);
    den1 += __shfl_xor_sync(0xffffffffu, den1, 2);
    if ((lane & 3) == 0) {
        if (v0) g_den[js * N_NODES + r0] = den0;
        if (v1) g_den[js * N_NODES + r1] = den1;
    }
    // accumulator partials
    float* pb = g_part + (size_t)js * N_NODES * OUT_F;
    #pragma unroll
    for (int np = 0; np < 16; np++) {
        int col = np * 8 + cq;
        if (v0) *(float2*)(pb + (size_t)r0 * OUT_F + col) = make_float2(acc[np][0], acc[np][1]);
        if (v1) *(float2*)(pb + (size_t)r1 * OUT_F + col) = make_float2(acc[np][2], acc[np][3]);
    }
}

// ================= K4: reduce splits, normalize, ELU, store =================
__global__ void k_final(float* __restrict__ out) {
    int gid = blockIdx.x * blockDim.x + threadIdx.x;   // one float4 each
    int row = gid >> 5;
    int f = (gid & 31) * 4;
    if (row >= N_NODES) return;
    float4 s = make_float4(0.f, 0.f, 0.f, 0.f);
    float den = 0.f;
    #pragma unroll
    for (int sp = 0; sp < JSPLIT; sp++) {
        const float4 p = *(const float4*)(g_part + ((size_t)sp * N_NODES + row) * OUT_F + f);
        s.x += p.x; s.y += p.y; s.z += p.z; s.w += p.w;
        den += g_den[sp * N_NODES + row];
    }
    float inv = (den > 0.f) ? 1.f / den : 0.f;
    float o[4] = {s.x * inv, s.y * inv, s.z * inv, s.w * inv};
    #pragma unroll
    for (int e = 0; e < 4; e++) o[e] = (o[e] > 0.f) ? o[e] : expm1f(o[e]);
    *(float4*)(out + (size_t)row * OUT_F + f) = make_float4(o[0], o[1], o[2], o[3]);
}

extern "C" void kernel_launch(void* const* d_in, const int* in_sizes, int n_in,
                              void* d_out, int out_size) {
    const float* node_emb = (const float*)d_in[0];
    const float* attr_emb = (const float*)d_in[1];
    const int*   feat     = (const int*)d_in[2];
    const float* W        = (const float*)d_in[3];
    const float* a        = (const float*)d_in[4];
    float* out = (float*)d_out;

    cudaFuncSetAttribute(k_mainT, cudaFuncAttributeMaxDynamicSharedMemorySize, SMEM_BYTES);

    k_v1<<<(IN_F + 255) / 256, 256>>>(W, a);                 // idx 0
    k_attr<<<(N_ATTRS + 63) / 64, 256>>>(attr_emb, W, a);    // idx 1
    k_node<<<(N_NODES * 32 + 255) / 256, 256>>>(node_emb);   // idx 2
    k_mainT<<<N_CTAS_N * JSPLIT, 256, SMEM_BYTES>>>(feat);   // idx 3 (profiled)
    k_final<<<(N_NODES * 32 + 255) / 256, 256>>>(out);       // idx 4
}

// round 8
// speedup vs baseline: 5.8018x; 1.0356x over previous
#include <cuda_runtime.h>
#include <cuda_fp16.h>
#include <cstdint>

#define N_NODES 20000
#define N_ATTRS 5000
#define IN_F 512
#define OUT_F 128
#define LRELU_ALPHA 0.2f

#define M_TILE 128
#define JT 64
#define VT_LD 5056           // padded attr count (79*64)
#define NT_J 79              // total 64-attr tiles
#define JSPLIT 4
#define TPS 20               // tiles per split (last split gets 19)
#define N_CTAS_N 157         // ceil(20000/128)
#define VROW 144             // smem V row pitch (bytes): conflict-free ldmatrix
#define VTILE (128 * VROW)   // 18432 B per fp16 tile
#define NBUF 3
#define SQQ_OFF (NBUF * VTILE)               // 55296
#define SMEM_BYTES (SQQ_OFF + TPS * JT * 8)  // 65536

typedef unsigned long long ull;
typedef unsigned int u32;

// ---------------- scratch (no cudaMalloc allowed) ----------------
__device__ __align__(16) float g_v1[IN_F];
__device__ __align__(16) float g_P[N_NODES];     // scaled exp(s)
__device__ __align__(16) float g_Pa[N_NODES];    // scaled exp(alpha*s)
__device__ __align__(16) float g_sc[N_NODES];    // per-node scale
__device__ __align__(16) float g_Q[VT_LD];
__device__ __align__(16) float g_Qa[VT_LD];
__device__ __align__(16) __half g_vt[(size_t)OUT_F * VT_LD];   // V^T fp16
__device__ __align__(16) float g_part[(size_t)JSPLIT * N_NODES * OUT_F];
__device__ __align__(16) float g_den[JSPLIT * N_NODES];
__device__ int g_qmax_i;

// ---------------- helpers ----------------
__device__ __forceinline__ u32 smem_u32(const void* p) {
    u32 a;
    asm("{ .reg .u64 t; cvta.to.shared.u64 t, %1; cvt.u32.u64 %0, t; }" : "=r"(a) : "l"(p));
    return a;
}
__device__ __forceinline__ void cp_async16(u32 smem, const void* gmem) {
    asm volatile("cp.async.cg.shared.global [%0], [%1], 16;" :: "r"(smem), "l"(gmem));
}
#define CP_COMMIT() asm volatile("cp.async.commit_group;")

__device__ __forceinline__ u32 cvt_f16x2(float lo, float hi) {
    u32 r;
    asm("cvt.rn.f16x2.f32 %0, %1, %2;" : "=r"(r) : "f"(hi), "f"(lo));
    return r;
}
#define LDSM4(r0, r1, r2, r3, addr) \
    asm volatile("ldmatrix.sync.aligned.m8n8.x4.shared.b16 {%0,%1,%2,%3}, [%4];" \
        : "=r"(r0), "=r"(r1), "=r"(r2), "=r"(r3) : "r"(addr))

__device__ __forceinline__ void mma16816(float* c, u32 a0, u32 a1, u32 a2, u32 a3,
                                         u32 b0, u32 b1) {
    asm volatile("mma.sync.aligned.m16n8k16.row.col.f32.f16.f16.f32 "
        "{%0,%1,%2,%3}, {%4,%5,%6,%7}, {%8,%9}, {%0,%1,%2,%3};"
        : "+f"(c[0]), "+f"(c[1]), "+f"(c[2]), "+f"(c[3])
        : "r"(a0), "r"(a1), "r"(a2), "r"(a3), "r"(b0), "r"(b1));
}
// scaled weight: w' = m * ( P'q >= sc ? P'q : Pa'qa )
__device__ __forceinline__ float wfun(int m, float P, float Pa, float sc, float q, float qa) {
    float pq = P * q;
    float w = (pq >= sc) ? pq : Pa * qa;
    return (m > 0) ? w : 0.f;
}

// ================= K0: v1 = W @ a1 ; zero pads; reset qmax =================
__global__ void k_v1(const float* __restrict__ W, const float* __restrict__ a) {
    __shared__ float sa[OUT_F];
    if (threadIdx.x < OUT_F) sa[threadIdx.x] = a[threadIdx.x];
    __syncthreads();
    int k = blockIdx.x * blockDim.x + threadIdx.x;
    if (k < IN_F) {
        const float* wr = W + (size_t)k * OUT_F;
        float s = 0.f;
        #pragma unroll 16
        for (int f = 0; f < OUT_F; f++) s += wr[f] * sa[f];
        g_v1[k] = s;
    }
    if (blockIdx.x == 0) {
        int tid = threadIdx.x;
        if (tid == 0) g_qmax_i = 0;
        if (tid < VT_LD - N_ATTRS) {        // 56
            g_Q[N_ATTRS + tid] = 0.f;
            g_Qa[N_ATTRS + tid] = 0.f;
        }
        // zero g_vt pad columns j in [5000, 5056) for all 128 f-rows
        u32* vt32 = (u32*)g_vt;
        for (int idx = tid; idx < 128 * 28; idx += 256) {
            int f = idx / 28, c = idx % 28;
            vt32[((size_t)f * VT_LD + N_ATTRS) / 2 + c] = 0u;
        }
    }
}

// ================= K1: attr_h = attr_emb @ W ; Q,Qa ; V^T fp16 ; qmax =====
__global__ void k_attr(const float* __restrict__ ae, const float* __restrict__ Wm,
                       const float* __restrict__ a) {
    __shared__ float sA[64][32];
    __shared__ float sW[32][OUT_F];
    int tid = threadIdx.x;
    int r0 = blockIdx.x * 64;
    int wr = tid >> 5;
    int lane = tid & 31;
    float acc[8][4];
    #pragma unroll
    for (int i = 0; i < 8; i++)
        #pragma unroll
        for (int c = 0; c < 4; c++) acc[i][c] = 0.f;

    for (int k0 = 0; k0 < IN_F; k0 += 32) {
        __syncthreads();
        #pragma unroll
        for (int it = 0; it < 8; it++) {
            int idx = tid + 256 * it;
            int r = idx >> 5, kk = idx & 31;
            int gr = r0 + r;
            sA[r][kk] = (gr < N_ATTRS) ? ae[(size_t)gr * IN_F + k0 + kk] : 0.f;
        }
        #pragma unroll
        for (int it = 0; it < 4; it++) {
            int idx = tid + 256 * it;
            int kk = idx >> 5, f4 = idx & 31;
            *(float4*)&sW[kk][f4 * 4] = *(const float4*)(Wm + (size_t)(k0 + kk) * OUT_F + f4 * 4);
        }
        __syncthreads();
        #pragma unroll 8
        for (int kk = 0; kk < 32; kk++) {
            float4 wv = *(float4*)&sW[kk][lane * 4];
            #pragma unroll
            for (int r = 0; r < 8; r++) {
                float av = sA[wr * 8 + r][kk];
                acc[r][0] += av * wv.x;
                acc[r][1] += av * wv.y;
                acc[r][2] += av * wv.z;
                acc[r][3] += av * wv.w;
            }
        }
    }
    // V^T fp16: thread owns cols f = lane*4..+3, rows j = r0+wr*8 .. +7
    #pragma unroll
    for (int c = 0; c < 4; c++) {
        u32 p[4];
        #pragma unroll
        for (int k = 0; k < 4; k++)
            p[k] = cvt_f16x2(acc[2 * k][c], acc[2 * k + 1][c]);
        int jbase = r0 + wr * 8;
        if (jbase < N_ATTRS) {
            size_t off = (size_t)(lane * 4 + c) * VT_LD + jbase;
            *(uint4*)&g_vt[off] = make_uint4(p[0], p[1], p[2], p[3]);
        }
    }
    // scores
    float4 a2v = *(const float4*)(a + OUT_F + lane * 4);
    float qmax = 0.f;
    #pragma unroll
    for (int r = 0; r < 8; r++) {
        int gr = r0 + wr * 8 + r;
        float t = acc[r][0] * a2v.x + acc[r][1] * a2v.y + acc[r][2] * a2v.z + acc[r][3] * a2v.w;
        #pragma unroll
        for (int o = 16; o > 0; o >>= 1) t += __shfl_xor_sync(0xffffffffu, t, o);
        if (gr < N_ATTRS) {
            float Q = expf(t);
            if (lane == 0) {
                g_Q[gr]  = Q;
                g_Qa[gr] = expf(LRELU_ALPHA * t);
            }
            if (Q > qmax) qmax = Q;
        }
    }
    if (lane == 0) atomicMax(&g_qmax_i, __float_as_int(qmax));
}

// ================= K2: node scores -> scaled P, Pa, sc =================
__global__ void k_node(const float* __restrict__ ne) {
    int gw = (blockIdx.x * blockDim.x + threadIdx.x) >> 5;
    int lane = threadIdx.x & 31;
    if (gw >= N_NODES) return;
    const float4* row = (const float4*)(ne + (size_t)gw * IN_F);
    const float4* v1 = (const float4*)g_v1;
    float s = 0.f;
    #pragma unroll
    for (int t = 0; t < 4; t++) {
        float4 x = row[lane + 32 * t];
        float4 c = v1[lane + 32 * t];
        s += x.x * c.x + x.y * c.y + x.z * c.z + x.w * c.w;
    }
    #pragma unroll
    for (int o = 16; o > 0; o >>= 1) s += __shfl_xor_sync(0xffffffffu, s, o);
    if (lane == 0) {
        float P  = expf(s);
        float Pa = expf(LRELU_ALPHA * s);
        float Qmax = __int_as_float(g_qmax_i);
        float wmax = P * Qmax;
        if (wmax < 1.f) wmax = 1.f;
        float sc = 1.f / wmax;
        g_P[gw]  = P * sc;
        g_Pa[gw] = Pa * sc;
        g_sc[gw] = sc;
    }
}

// ================= K3: fp16 HMMA fused attention (split-j partials) =========
// CTA = 128 nodes x 128 feats x <=20 contiguous 64-attr tiles. 8 warps.
// 3-stage cp.async V pipeline (1 barrier/tile); feat prefetch distance 2
// (parity registers, no copies); LDSM pipelined distance-2 inside each slice.
__global__ __launch_bounds__(256, 2) void k_mainT(const int* __restrict__ feat) {
    extern __shared__ char dsm[];
    const u32 smB = smem_u32(dsm);
    float* sQQ = (float*)(dsm + SQQ_OFF);    // interleaved (q, qa) pairs
    const int tid = threadIdx.x;
    const int wid = tid >> 5, lane = tid & 31;
    const int js = blockIdx.x & 3;
    const int n0 = (blockIdx.x >> 2) * M_TILE;
    const int t0 = js * TPS;
    const int NT = (NT_J - t0 < TPS) ? (NT_J - t0) : TPS;
    const int NS = NT * 4;                  // total k-slices
    const int jg0 = t0 * JT;                // contiguous split base

    // stage interleaved Q/Qa for this split
    for (int idx = tid; idx < NT * JT; idx += 256) {
        sQQ[2 * idx]     = g_Q[jg0 + idx];
        sQQ[2 * idx + 1] = g_Qa[jg0 + idx];
    }

    const int r0 = n0 + wid * 16 + (lane >> 2);
    const int r1 = r0 + 8;
    const int cq = (lane & 3) * 2;
    const bool v0 = r0 < N_NODES, v1 = r1 < N_NODES;
    const float P0  = v0 ? g_P[r0]  : 0.f;
    const float Pa0 = v0 ? g_Pa[r0] : 0.f;
    const float s0  = v0 ? g_sc[r0] : 1.f;
    const float P1  = v1 ? g_P[r1]  : 0.f;
    const float Pa1 = v1 ? g_Pa[r1] : 0.f;
    const float s1  = v1 ? g_sc[r1] : 1.f;
    const int* fr0 = feat + (size_t)r0 * N_ATTRS;
    const int* fr1 = feat + (size_t)r1 * N_ATTRS;

    float acc[16][4];
    #pragma unroll
    for (int i = 0; i < 16; i++)
        #pragma unroll
        for (int c = 0; c < 4; c++) acc[i][c] = 0.f;
    float den0 = 0.f, den1 = 0.f;

    const u32 lmoff = (u32)(((lane & 7) + ((lane & 16) >> 1)) * VROW + ((lane & 8) >> 3) * 16);

    auto loadV = [&](int kt) {
        const int j0 = jg0 + kt * JT;
        const u32 dst = smB + (kt % NBUF) * VTILE;
        #pragma unroll
        for (int t = 0; t < 4; t++) {
            int id = tid + 256 * t;          // 1024 chunks of 16B
            int f = id >> 3, c = id & 7;
            cp_async16(dst + (u32)(f * VROW + c * 16),
                       g_vt + (size_t)f * VT_LD + j0 + c * 8);
        }
        CP_COMMIT();
    };
    // feat prefetch for slice s into parity register set
    auto prefetchF = [&](int s, int2* pm) {
        const int c0 = jg0 + s * 16 + cq;
        const int c8 = c0 + 8;
        bool in = s < NS;
        pm[0] = (in && v0 && c0 < N_ATTRS) ? __ldg((const int2*)(fr0 + c0)) : make_int2(0, 0);
        pm[1] = (in && v0 && c8 < N_ATTRS) ? __ldg((const int2*)(fr0 + c8)) : make_int2(0, 0);
        pm[2] = (in && v1 && c0 < N_ATTRS) ? __ldg((const int2*)(fr1 + c0)) : make_int2(0, 0);
        pm[3] = (in && v1 && c8 < N_ATTRS) ? __ldg((const int2*)(fr1 + c8)) : make_int2(0, 0);
    };

    int2 pm[2][4];                           // parity: slice s lives in pm[s&1]
    loadV(0);
    if (NT > 1) loadV(1);
    prefetchF(0, pm[0]);
    prefetchF(1, pm[1]);

    for (int kt = 0; kt < NT; kt++) {
        // tile kt's V buffer complete; at most 1 group (kt+1) pending
        asm volatile("cp.async.wait_group 1;" ::: "memory");
        __syncthreads();                 // single barrier per tile
        if (kt + 2 < NT) loadV(kt + 2);  // overwrites buf read at kt-1: safe post-barrier

        const u32 vb = smB + (kt % NBUF) * VTILE;
        #pragma unroll
        for (int ks = 0; ks < 4; ks++) {
            const int s = kt * 4 + ks;
            const int par = ks & 1;          // static per unrolled ks
            const int2 m00 = pm[par][0], m08 = pm[par][1];
            const int2 m10 = pm[par][2], m18 = pm[par][3];
            prefetchF(s + 2, pm[par]);       // refill same parity for slice s+2

            const u32 bbase = vb + lmoff + ks * 32;
            // LDSM ring: distance-2 pipelined (b latency hidden under MMAs)
            u32 br[3][4];
            LDSM4(br[0][0], br[0][1], br[0][2], br[0][3], bbase);
            LDSM4(br[1][0], br[1][1], br[1][2], br[1][3], bbase + 16 * VROW);

            const int jl = kt * JT + ks * 16 + cq;  // local index into sQQ pairs
            const float4 qq0 = *(const float4*)&sQQ[2 * jl];        // q,qa @ jl, jl+1
            const float4 qq8 = *(const float4*)&sQQ[2 * (jl + 8)];  // q,qa @ jl+8, jl+9

            float w00 = wfun(m00.x, P0, Pa0, s0, qq0.x, qq0.y);
            float w01 = wfun(m00.y, P0, Pa0, s0, qq0.z, qq0.w);
            float w08 = wfun(m08.x, P0, Pa0, s0, qq8.x, qq8.y);
            float w09 = wfun(m08.y, P0, Pa0, s0, qq8.z, qq8.w);
            float w10 = wfun(m10.x, P1, Pa1, s1, qq0.x, qq0.y);
            float w11 = wfun(m10.y, P1, Pa1, s1, qq0.z, qq0.w);
            float w18 = wfun(m18.x, P1, Pa1, s1, qq8.x, qq8.y);
            float w19 = wfun(m18.y, P1, Pa1, s1, qq8.z, qq8.w);
            den0 += (w00 + w01) + (w08 + w09);
            den1 += (w10 + w11) + (w18 + w19);

            const u32 a0 = cvt_f16x2(w00, w01);
            const u32 a1 = cvt_f16x2(w10, w11);
            const u32 a2 = cvt_f16x2(w08, w09);
            const u32 a3 = cvt_f16x2(w18, w19);

            #pragma unroll
            for (int np = 0; np < 8; np++) {
                const int cur = np % 3;
                if (np < 6) {
                    const int nxt = (np + 2) % 3;
                    LDSM4(br[nxt][0], br[nxt][1], br[nxt][2], br[nxt][3],
                          bbase + (np + 2) * 16 * VROW);
                }
                mma16816(acc[2 * np],     a0, a1, a2, a3, br[cur][0], br[cur][1]);
                mma16816(acc[2 * np + 1], a0, a1, a2, a3, br[cur][2], br[cur][3]);
            }
        }
    }

    // denominator partials (4 lanes share each row)
    den0 += __shfl_xor_sync(0xffffffffu, den0, 1);
    den0 += __shfl_xor_sync(0xffffffffu, den0, 2);
    den1 += __shfl_xor_sync(0xffffffffu, den1, 1);
    den1 += __shfl_xor_sync(0xffffffffu, den1, 2);
    if ((lane & 3) == 0) {
        if (v0) g_den[js * N_NODES + r0] = den0;
        if (v1) g_den[js * N_NODES + r1] = den1;
    }
    // accumulator partials
    float* pb = g_part + (size_t)js * N_NODES * OUT_F;
    #pragma unroll
    for (int np = 0; np < 16; np++) {
        int col = np * 8 + cq;
        if (v0) *(float2*)(pb + (size_t)r0 * OUT_F + col) = make_float2(acc[np][0], acc[np][1]);
        if (v1) *(float2*)(pb + (size_t)r1 * OUT_F + col) = make_float2(acc[np][2], acc[np][3]);
    }
}

// ================= K4: reduce splits, normalize, ELU, store =================
__global__ void k_final(float* __restrict__ out) {
    int gid = blockIdx.x * blockDim.x + threadIdx.x;   // one float4 each
    int row = gid >> 5;
    int f = (gid & 31) * 4;
    if (row >= N_NODES) return;
    float4 s = make_float4(0.f, 0.f, 0.f, 0.f);
    float den = 0.f;
    #pragma unroll
    for (int sp = 0; sp < JSPLIT; sp++) {
        const float4 p = *(const float4*)(g_part + ((size_t)sp * N_NODES + row) * OUT_F + f);
        s.x += p.x; s.y += p.y; s.z += p.z; s.w += p.w;
        den += g_den[sp * N_NODES + row];
    }
    float inv = (den > 0.f) ? 1.f / den : 0.f;
    float o[4] = {s.x * inv, s.y * inv, s.z * inv, s.w * inv};
    #pragma unroll
    for (int e = 0; e < 4; e++) o[e] = (o[e] > 0.f) ? o[e] : expm1f(o[e]);
    *(float4*)(out + (size_t)row * OUT_F + f) = make_float4(o[0], o[1], o[2], o[3]);
}

extern "C" void kernel_launch(void* const* d_in, const int* in_sizes, int n_in,
                              void* d_out, int out_size) {
    const float* node_emb = (const float*)d_in[0];
    const float* attr_emb = (const float*)d_in[1];
    const int*   feat     = (const int*)d_in[2];
    const float* W        = (const float*)d_in[3];
    const float* a        = (const float*)d_in[4];
    float* out = (float*)d_out;

    cudaFuncSetAttribute(k_mainT, cudaFuncAttributeMaxDynamicSharedMemorySize, SMEM_BYTES);

    k_v1<<<(IN_F + 255) / 256, 256>>>(W, a);                 // idx 0
    k_attr<<<(N_ATTRS + 63) / 64, 256>>>(attr_emb, W, a);    // idx 1
    k_node<<<(N_NODES * 32 + 255) / 256, 256>>>(node_emb);   // idx 2
    k_mainT<<<N_CTAS_N * JSPLIT, 256, SMEM_BYTES>>>(feat);   // idx 3 (profiled)
    k_final<<<(N_NODES * 32 + 255) / 256, 256>>>(out);       // idx 4
}

// round 9
// speedup vs baseline: 6.6940x; 1.1538x over previous
#include <cuda_runtime.h>
#include <cuda_fp16.h>
#include <cstdint>

#define N_NODES 20000
#define N_ATTRS 5000
#define IN_F 512
#define OUT_F 128
#define LRELU_ALPHA 0.2f

#define M_TILE 128
#define JT 64
#define VT_LD 5056           // padded attr count (79*64)
#define NT_J 79              // total 64-attr tiles
#define JSPLIT 4
#define TPS 20               // tiles per split (last split gets 19)
#define N_CTAS_N 157         // ceil(20000/128)
#define VROW 144             // smem V row pitch (bytes): conflict-free ldmatrix
#define VTILE (128 * VROW)   // 18432 B per fp16 tile
#define FTILE 32768          // 128 rows x 256B (64 attrs x int32), XOR-swizzled
#define SMF_OFF (2 * VTILE)               // 36864
#define SQQ_OFF (SMF_OFF + 2 * FTILE)     // 102400
#define SMEM_BYTES (SQQ_OFF + TPS * JT * 8)  // 112640

typedef unsigned long long ull;
typedef unsigned int u32;

// ---------------- scratch (no cudaMalloc allowed) ----------------
__device__ __align__(16) float g_v1[IN_F];
__device__ __align__(16) float g_P[N_NODES];     // scaled exp(s)
__device__ __align__(16) float g_Pa[N_NODES];    // scaled exp(alpha*s)
__device__ __align__(16) float g_sc[N_NODES];    // per-node scale
__device__ __align__(16) float g_Q[VT_LD];
__device__ __align__(16) float g_Qa[VT_LD];
__device__ __align__(16) __half g_vt[(size_t)OUT_F * VT_LD];   // V^T fp16
__device__ __align__(16) float g_part[(size_t)JSPLIT * N_NODES * OUT_F];
__device__ __align__(16) float g_den[JSPLIT * N_NODES];
__device__ int g_qmax_i;

// ---------------- helpers ----------------
__device__ __forceinline__ u32 smem_u32(const void* p) {
    u32 a;
    asm("{ .reg .u64 t; cvta.to.shared.u64 t, %1; cvt.u32.u64 %0, t; }" : "=r"(a) : "l"(p));
    return a;
}
__device__ __forceinline__ void cp_async16(u32 smem, const void* gmem) {
    asm volatile("cp.async.cg.shared.global [%0], [%1], 16;" :: "r"(smem), "l"(gmem));
}
#define CP_COMMIT() asm volatile("cp.async.commit_group;")

__device__ __forceinline__ u32 cvt_f16x2(float lo, float hi) {
    u32 r;
    asm("cvt.rn.f16x2.f32 %0, %1, %2;" : "=r"(r) : "f"(hi), "f"(lo));
    return r;
}
#define LDSM4(r0, r1, r2, r3, addr) \
    asm volatile("ldmatrix.sync.aligned.m8n8.x4.shared.b16 {%0,%1,%2,%3}, [%4];" \
        : "=r"(r0), "=r"(r1), "=r"(r2), "=r"(r3) : "r"(addr))

__device__ __forceinline__ void mma16816(float* c, u32 a0, u32 a1, u32 a2, u32 a3,
                                         u32 b0, u32 b1) {
    asm volatile("mma.sync.aligned.m16n8k16.row.col.f32.f16.f16.f32 "
        "{%0,%1,%2,%3}, {%4,%5,%6,%7}, {%8,%9}, {%0,%1,%2,%3};"
        : "+f"(c[0]), "+f"(c[1]), "+f"(c[2]), "+f"(c[3])
        : "r"(a0), "r"(a1), "r"(a2), "r"(a3), "r"(b0), "r"(b1));
}
// scaled weight: w' = m * ( P'q >= sc ? P'q : Pa'qa )
__device__ __forceinline__ float wfun(int m, float P, float Pa, float sc, float q, float qa) {
    float pq = P * q;
    float w = (pq >= sc) ? pq : Pa * qa;
    return (m > 0) ? w : 0.f;
}

// ================= K0: v1 = W @ a1 ; zero pads; reset qmax =================
__global__ void k_v1(const float* __restrict__ W, const float* __restrict__ a) {
    __shared__ float sa[OUT_F];
    if (threadIdx.x < OUT_F) sa[threadIdx.x] = a[threadIdx.x];
    __syncthreads();
    int k = blockIdx.x * blockDim.x + threadIdx.x;
    if (k < IN_F) {
        const float* wr = W + (size_t)k * OUT_F;
        float s = 0.f;
        #pragma unroll 16
        for (int f = 0; f < OUT_F; f++) s += wr[f] * sa[f];
        g_v1[k] = s;
    }
    if (blockIdx.x == 0) {
        int tid = threadIdx.x;
        if (tid == 0) g_qmax_i = 0;
        if (tid < VT_LD - N_ATTRS) {        // 56
            g_Q[N_ATTRS + tid] = 0.f;
            g_Qa[N_ATTRS + tid] = 0.f;
        }
        // zero g_vt pad columns j in [5000, 5056) for all 128 f-rows
        u32* vt32 = (u32*)g_vt;
        for (int idx = tid; idx < 128 * 28; idx += 256) {
            int f = idx / 28, c = idx % 28;
            vt32[((size_t)f * VT_LD + N_ATTRS) / 2 + c] = 0u;
        }
    }
}

// ================= K1: attr_h = attr_emb @ W ; Q,Qa ; V^T fp16 ; qmax =====
__global__ void k_attr(const float* __restrict__ ae, const float* __restrict__ Wm,
                       const float* __restrict__ a) {
    __shared__ float sA[64][32];
    __shared__ float sW[32][OUT_F];
    int tid = threadIdx.x;
    int r0 = blockIdx.x * 64;
    int wr = tid >> 5;
    int lane = tid & 31;
    float acc[8][4];
    #pragma unroll
    for (int i = 0; i < 8; i++)
        #pragma unroll
        for (int c = 0; c < 4; c++) acc[i][c] = 0.f;

    for (int k0 = 0; k0 < IN_F; k0 += 32) {
        __syncthreads();
        #pragma unroll
        for (int it = 0; it < 8; it++) {
            int idx = tid + 256 * it;
            int r = idx >> 5, kk = idx & 31;
            int gr = r0 + r;
            sA[r][kk] = (gr < N_ATTRS) ? ae[(size_t)gr * IN_F + k0 + kk] : 0.f;
        }
        #pragma unroll
        for (int it = 0; it < 4; it++) {
            int idx = tid + 256 * it;
            int kk = idx >> 5, f4 = idx & 31;
            *(float4*)&sW[kk][f4 * 4] = *(const float4*)(Wm + (size_t)(k0 + kk) * OUT_F + f4 * 4);
        }
        __syncthreads();
        #pragma unroll 8
        for (int kk = 0; kk < 32; kk++) {
            float4 wv = *(float4*)&sW[kk][lane * 4];
            #pragma unroll
            for (int r = 0; r < 8; r++) {
                float av = sA[wr * 8 + r][kk];
                acc[r][0] += av * wv.x;
                acc[r][1] += av * wv.y;
                acc[r][2] += av * wv.z;
                acc[r][3] += av * wv.w;
            }
        }
    }
    // V^T fp16: thread owns cols f = lane*4..+3, rows j = r0+wr*8 .. +7
    #pragma unroll
    for (int c = 0; c < 4; c++) {
        u32 p[4];
        #pragma unroll
        for (int k = 0; k < 4; k++)
            p[k] = cvt_f16x2(acc[2 * k][c], acc[2 * k + 1][c]);
        int jbase = r0 + wr * 8;
        if (jbase < N_ATTRS) {
            size_t off = (size_t)(lane * 4 + c) * VT_LD + jbase;
            *(uint4*)&g_vt[off] = make_uint4(p[0], p[1], p[2], p[3]);
        }
    }
    // scores
    float4 a2v = *(const float4*)(a + OUT_F + lane * 4);
    float qmax = 0.f;
    #pragma unroll
    for (int r = 0; r < 8; r++) {
        int gr = r0 + wr * 8 + r;
        float t = acc[r][0] * a2v.x + acc[r][1] * a2v.y + acc[r][2] * a2v.z + acc[r][3] * a2v.w;
        #pragma unroll
        for (int o = 16; o > 0; o >>= 1) t += __shfl_xor_sync(0xffffffffu, t, o);
        if (gr < N_ATTRS) {
            float Q = expf(t);
            if (lane == 0) {
                g_Q[gr]  = Q;
                g_Qa[gr] = expf(LRELU_ALPHA * t);
            }
            if (Q > qmax) qmax = Q;
        }
    }
    if (lane == 0) atomicMax(&g_qmax_i, __float_as_int(qmax));
}

// ================= K2: node scores -> scaled P, Pa, sc =================
__global__ void k_node(const float* __restrict__ ne) {
    int gw = (blockIdx.x * blockDim.x + threadIdx.x) >> 5;
    int lane = threadIdx.x & 31;
    if (gw >= N_NODES) return;
    const float4* row = (const float4*)(ne + (size_t)gw * IN_F);
    const float4* v1 = (const float4*)g_v1;
    float s = 0.f;
    #pragma unroll
    for (int t = 0; t < 4; t++) {
        float4 x = row[lane + 32 * t];
        float4 c = v1[lane + 32 * t];
        s += x.x * c.x + x.y * c.y + x.z * c.z + x.w * c.w;
    }
    #pragma unroll
    for (int o = 16; o > 0; o >>= 1) s += __shfl_xor_sync(0xffffffffu, s, o);
    if (lane == 0) {
        float P  = expf(s);
        float Pa = expf(LRELU_ALPHA * s);
        float Qmax = __int_as_float(g_qmax_i);
        float wmax = P * Qmax;
        if (wmax < 1.f) wmax = 1.f;
        float sc = 1.f / wmax;
        g_P[gw]  = P * sc;
        g_Pa[gw] = Pa * sc;
        g_sc[gw] = sc;
    }
}

// ================= K3: fp16 HMMA fused attention (split-j partials) =========
// CTA = 128 nodes x 128 feats x <=20 contiguous 64-attr tiles. 8 warps.
// feat AND V both bulk-streamed via cp.async (2-stage, 1 commit group + 1
// barrier per tile). feat smem rows XOR-swizzled; mask values read by LDS
// with distance-2 parity prefetch. LDSM distance-2 ring for V.
__global__ __launch_bounds__(256, 2) void k_mainT(const int* __restrict__ feat) {
    extern __shared__ char dsm[];
    const u32 smB = smem_u32(dsm);           // V tiles
    const u32 smF = smB + SMF_OFF;           // feat tiles
    float* sQQ = (float*)(dsm + SQQ_OFF);    // interleaved (q, qa) pairs
    const int tid = threadIdx.x;
    const int wid = tid >> 5, lane = tid & 31;
    const int js = blockIdx.x & 3;
    const int n0 = (blockIdx.x >> 2) * M_TILE;
    const int t0 = js * TPS;
    const int NT = (NT_J - t0 < TPS) ? (NT_J - t0) : TPS;
    const int jg0 = t0 * JT;                // contiguous split base

    // stage interleaved Q/Qa for this split
    for (int idx = tid; idx < NT * JT; idx += 256) {
        sQQ[2 * idx]     = g_Q[jg0 + idx];
        sQQ[2 * idx + 1] = g_Qa[jg0 + idx];
    }

    const int rrow = wid * 16 + (lane >> 2);   // local row 0..127
    const int r0 = n0 + rrow;
    const int r1 = r0 + 8;
    const int cq = (lane & 3) * 2;
    const bool v0 = r0 < N_NODES, v1 = r1 < N_NODES;
    const float P0  = v0 ? g_P[r0]  : 0.f;
    const float Pa0 = v0 ? g_Pa[r0] : 0.f;
    const float s0  = v0 ? g_sc[r0] : 1.f;
    const float P1  = v1 ? g_P[r1]  : 0.f;
    const float Pa1 = v1 ? g_Pa[r1] : 0.f;
    const float s1  = v1 ? g_sc[r1] : 1.f;

    float acc[16][4];
    #pragma unroll
    for (int i = 0; i < 16; i++)
        #pragma unroll
        for (int c = 0; c < 4; c++) acc[i][c] = 0.f;
    float den0 = 0.f, den1 = 0.f;

    const u32 lmoff = (u32)(((lane & 7) + ((lane & 16) >> 1)) * VROW + ((lane & 8) >> 3) * 16);
    // feat LDS addressing (row pitch 256B, chunk XOR row&7 swizzle)
    const u32 frow0 = (u32)(rrow * 256);
    const int xr = rrow & 7;                  // same for rrow and rrow+8
    const u32 boff = (u32)((cq & 2) << 2);    // byte offset within 16B chunk
    const int cbase = cq >> 2;                // chunk sub-index from cq

    auto loadV = [&](int kt) {
        const int j0 = jg0 + kt * JT;
        const u32 dst = smB + (kt & 1) * VTILE;
        #pragma unroll
        for (int t = 0; t < 4; t++) {
            int id = tid + 256 * t;          // 1024 chunks of 16B
            int f = id >> 3, c = id & 7;
            cp_async16(dst + (u32)(f * VROW + c * 16),
                       g_vt + (size_t)f * VT_LD + j0 + c * 8);
        }
    };
    auto loadF = [&](int kt) {
        const int j0 = jg0 + kt * JT;
        const u32 dst = smF + (kt & 1) * FTILE;
        #pragma unroll
        for (int t = 0; t < 8; t++) {
            int id = tid + 256 * t;          // 2048 chunks of 16B
            int row = id >> 4, chunk = id & 15;
            int gr = n0 + row;
            if (gr >= N_NODES) gr = N_NODES - 1;   // clamp: no fault, data unused
            int col = j0 + chunk * 4;
            if (col + 4 > N_ATTRS) col = j0;       // clamp pad cols (q=0 anyway)
            cp_async16(dst + (u32)(row * 256 + ((chunk ^ (row & 7)) << 4)),
                       feat + (size_t)gr * N_ATTRS + col);
        }
    };
    // feat mask LDS for slice ks of current tile into parity regs
    auto ldsF = [&](u32 fb, int ks, int2* pm) {
        int c0 = ks * 4 + cbase;
        u32 a00 = fb + frow0 + (u32)(((c0 ^ xr) << 4)) + boff;
        u32 a08 = fb + frow0 + (u32)((((c0 + 2) ^ xr) << 4)) + boff;
        asm volatile("ld.shared.v2.u32 {%0,%1}, [%2];" : "=r"(pm[0].x), "=r"(pm[0].y) : "r"(a00));
        asm volatile("ld.shared.v2.u32 {%0,%1}, [%2];" : "=r"(pm[1].x), "=r"(pm[1].y) : "r"(a08));
        asm volatile("ld.shared.v2.u32 {%0,%1}, [%2];" : "=r"(pm[2].x), "=r"(pm[2].y) : "r"(a00 + 2048));
        asm volatile("ld.shared.v2.u32 {%0,%1}, [%2];" : "=r"(pm[3].x), "=r"(pm[3].y) : "r"(a08 + 2048));
    };

    // prologue: stage tile 0
    loadF(0); loadV(0); CP_COMMIT();
    int2 pm[2][4];

    for (int kt = 0; kt < NT; kt++) {
        asm volatile("cp.async.wait_group 0;" ::: "memory");
        __syncthreads();                 // single barrier per tile
        if (kt + 1 < NT) { loadF(kt + 1); loadV(kt + 1); CP_COMMIT(); }

        const u32 vb = smB + (kt & 1) * VTILE;
        const u32 fb = smF + (kt & 1) * FTILE;
        ldsF(fb, 0, pm[0]);
        ldsF(fb, 1, pm[1]);

        #pragma unroll
        for (int ks = 0; ks < 4; ks++) {
            const int par = ks & 1;
            const int2 m00 = pm[par][0], m08 = pm[par][1];
            const int2 m10 = pm[par][2], m18 = pm[par][3];
            if (ks < 2) ldsF(fb, ks + 2, pm[par]);

            const u32 bbase = vb + lmoff + ks * 32;
            // LDSM ring: distance-2 pipelined
            u32 br[3][4];
            LDSM4(br[0][0], br[0][1], br[0][2], br[0][3], bbase);
            LDSM4(br[1][0], br[1][1], br[1][2], br[1][3], bbase + 16 * VROW);

            const int jl = kt * JT + ks * 16 + cq;  // local index into sQQ pairs
            const float4 qq0 = *(const float4*)&sQQ[2 * jl];
            const float4 qq8 = *(const float4*)&sQQ[2 * (jl + 8)];

            float w00 = wfun(m00.x, P0, Pa0, s0, qq0.x, qq0.y);
            float w01 = wfun(m00.y, P0, Pa0, s0, qq0.z, qq0.w);
            float w08 = wfun(m08.x, P0, Pa0, s0, qq8.x, qq8.y);
            float w09 = wfun(m08.y, P0, Pa0, s0, qq8.z, qq8.w);
            float w10 = wfun(m10.x, P1, Pa1, s1, qq0.x, qq0.y);
            float w11 = wfun(m10.y, P1, Pa1, s1, qq0.z, qq0.w);
            float w18 = wfun(m18.x, P1, Pa1, s1, qq8.x, qq8.y);
            float w19 = wfun(m18.y, P1, Pa1, s1, qq8.z, qq8.w);
            den0 += (w00 + w01) + (w08 + w09);
            den1 += (w10 + w11) + (w18 + w19);

            const u32 a0 = cvt_f16x2(w00, w01);
            const u32 a1 = cvt_f16x2(w10, w11);
            const u32 a2 = cvt_f16x2(w08, w09);
            const u32 a3 = cvt_f16x2(w18, w19);

            #pragma unroll
            for (int np = 0; np < 8; np++) {
                const int cur = np % 3;
                if (np < 6) {
                    const int nxt = (np + 2) % 3;
                    LDSM4(br[nxt][0], br[nxt][1], br[nxt][2], br[nxt][3],
                          bbase + (np + 2) * 16 * VROW);
                }
                mma16816(acc[2 * np],     a0, a1, a2, a3, br[cur][0], br[cur][1]);
                mma16816(acc[2 * np + 1], a0, a1, a2, a3, br[cur][2], br[cur][3]);
            }
        }
    }

    // denominator partials (4 lanes share each row)
    den0 += __shfl_xor_sync(0xffffffffu, den0, 1);
    den0 += __shfl_xor_sync(0xffffffffu, den0, 2);
    den1 += __shfl_xor_sync(0xffffffffu, den1, 1);
    den1 += __shfl_xor_sync(0xffffffffu, den1, 2);
    if ((lane & 3) == 0) {
        if (v0) g_den[js * N_NODES + r0] = den0;
        if (v1) g_den[js * N_NODES + r1] = den1;
    }
    // accumulator partials
    float* pb = g_part + (size_t)js * N_NODES * OUT_F;
    #pragma unroll
    for (int np = 0; np < 16; np++) {
        int col = np * 8 + cq;
        if (v0) *(float2*)(pb + (size_t)r0 * OUT_F + col) = make_float2(acc[np][0], acc[np][1]);
        if (v1) *(float2*)(pb + (size_t)r1 * OUT_F + col) = make_float2(acc[np][2], acc[np][3]);
    }
}

// ================= K4: reduce splits, normalize, ELU, store =================
__global__ void k_final(float* __restrict__ out) {
    int gid = blockIdx.x * blockDim.x + threadIdx.x;   // one float4 each
    int row = gid >> 5;
    int f = (gid & 31) * 4;
    if (row >= N_NODES) return;
    float4 s = make_float4(0.f, 0.f, 0.f, 0.f);
    float den = 0.f;
    #pragma unroll
    for (int sp = 0; sp < JSPLIT; sp++) {
        const float4 p = *(const float4*)(g_part + ((size_t)sp * N_NODES + row) * OUT_F + f);
        s.x += p.x; s.y += p.y; s.z += p.z; s.w += p.w;
        den += g_den[sp * N_NODES + row];
    }
    float inv = (den > 0.f) ? 1.f / den : 0.f;
    float o[4] = {s.x * inv, s.y * inv, s.z * inv, s.w * inv};
    #pragma unroll
    for (int e = 0; e < 4; e++) o[e] = (o[e] > 0.f) ? o[e] : expm1f(o[e]);
    *(float4*)(out + (size_t)row * OUT_F + f) = make_float4(o[0], o[1], o[2], o[3]);
}

extern "C" void kernel_launch(void* const* d_in, const int* in_sizes, int n_in,
                              void* d_out, int out_size) {
    const float* node_emb = (const float*)d_in[0];
    const float* attr_emb = (const float*)d_in[1];
    const int*   feat     = (const int*)d_in[2];
    const float* W        = (const float*)d_in[3];
    const float* a        = (const float*)d_in[4];
    float* out = (float*)d_out;

    cudaFuncSetAttribute(k_mainT, cudaFuncAttributeMaxDynamicSharedMemorySize, SMEM_BYTES);

    k_v1<<<(IN_F + 255) / 256, 256>>>(W, a);                 // idx 0
    k_attr<<<(N_ATTRS + 63) / 64, 256>>>(attr_emb, W, a);    // idx 1
    k_node<<<(N_NODES * 32 + 255) / 256, 256>>>(node_emb);   // idx 2
    k_mainT<<<N_CTAS_N * JSPLIT, 256, SMEM_BYTES>>>(feat);   // idx 3 (profiled)
    k_final<<<(N_NODES * 32 + 255) / 256, 256>>>(out);       // idx 4
}

// round 10
// speedup vs baseline: 6.7247x; 1.0046x over previous
#include <cuda_runtime.h>
#include <cuda_fp16.h>
#include <cstdint>

#define N_NODES 20000
#define N_ATTRS 5000
#define IN_F 512
#define OUT_F 128
#define LRELU_ALPHA 0.2f

#define M_TILE 128
#define JT 64
#define VT_LD 5056           // padded attr count (79*64)
#define NT_J 79              // total 64-attr tiles
#define JSPLIT 4
#define TPS 20               // tiles per split (last split gets 19)
#define N_CTAS_N 157         // ceil(20000/128)
#define VROW 144             // smem V row pitch (bytes): conflict-free ldmatrix
#define VTILE (128 * VROW)   // 18432 B per fp16 tile
#define FTILE 32768          // 128 rows x 256B (64 attrs x int32), XOR-swizzled
#define SMF_OFF (2 * VTILE)               // 36864
#define SQQ_OFF (SMF_OFF + 2 * FTILE)     // 102400
#define SMEM_BYTES (SQQ_OFF + TPS * JT * 8)  // 112640

typedef unsigned long long ull;
typedef unsigned int u32;

// ---------------- scratch (no cudaMalloc allowed) ----------------
__device__ __align__(16) float g_v1[IN_F];
__device__ __align__(16) float g_P[N_NODES];     // scaled exp(s)
__device__ __align__(16) float g_Pa[N_NODES];    // scaled exp(alpha*s)
__device__ __align__(16) float g_sc[N_NODES];    // per-node scale
__device__ __align__(16) float g_Q[VT_LD];
__device__ __align__(16) float g_Qa[VT_LD];
__device__ __align__(16) __half g_vt[(size_t)OUT_F * VT_LD];   // V^T fp16
__device__ __align__(16) float g_part[(size_t)JSPLIT * N_NODES * OUT_F];
__device__ __align__(16) float g_den[JSPLIT * N_NODES];
__device__ int g_qmax_i;

// ---------------- helpers ----------------
__device__ __forceinline__ u32 smem_u32(const void* p) {
    u32 a;
    asm("{ .reg .u64 t; cvta.to.shared.u64 t, %1; cvt.u32.u64 %0, t; }" : "=r"(a) : "l"(p));
    return a;
}
__device__ __forceinline__ void cp_async16(u32 smem, const void* gmem) {
    asm volatile("cp.async.cg.shared.global [%0], [%1], 16;" :: "r"(smem), "l"(gmem));
}
#define CP_COMMIT() asm volatile("cp.async.commit_group;")

__device__ __forceinline__ u32 cvt_f16x2(float lo, float hi) {
    u32 r;
    asm("cvt.rn.f16x2.f32 %0, %1, %2;" : "=r"(r) : "f"(hi), "f"(lo));
    return r;
}
#define LDSM4(r0, r1, r2, r3, addr) \
    asm volatile("ldmatrix.sync.aligned.m8n8.x4.shared.b16 {%0,%1,%2,%3}, [%4];" \
        : "=r"(r0), "=r"(r1), "=r"(r2), "=r"(r3) : "r"(addr))

__device__ __forceinline__ void mma16816(float* c, u32 a0, u32 a1, u32 a2, u32 a3,
                                         u32 b0, u32 b1) {
    asm volatile("mma.sync.aligned.m16n8k16.row.col.f32.f16.f16.f32 "
        "{%0,%1,%2,%3}, {%4,%5,%6,%7}, {%8,%9}, {%0,%1,%2,%3};"
        : "+f"(c[0]), "+f"(c[1]), "+f"(c[2]), "+f"(c[3])
        : "r"(a0), "r"(a1), "r"(a2), "r"(a3), "r"(b0), "r"(b1));
}
// scaled weight: w' = m * ( P'q >= sc ? P'q : Pa'qa )
__device__ __forceinline__ float wfun(int m, float P, float Pa, float sc, float q, float qa) {
    float pq = P * q;
    float w = (pq >= sc) ? pq : Pa * qa;
    return (m > 0) ? w : 0.f;
}

// ================= K0: v1 = W @ a1 ; zero pads; reset qmax =================
__global__ void k_v1(const float* __restrict__ W, const float* __restrict__ a) {
    __shared__ float sa[OUT_F];
    if (threadIdx.x < OUT_F) sa[threadIdx.x] = a[threadIdx.x];
    __syncthreads();
    int k = blockIdx.x * blockDim.x + threadIdx.x;
    if (k < IN_F) {
        const float* wr = W + (size_t)k * OUT_F;
        float s = 0.f;
        #pragma unroll 16
        for (int f = 0; f < OUT_F; f++) s += wr[f] * sa[f];
        g_v1[k] = s;
    }
    if (blockIdx.x == 0) {
        int tid = threadIdx.x;
        if (tid == 0) g_qmax_i = 0;
        if (tid < VT_LD - N_ATTRS) {        // 56
            g_Q[N_ATTRS + tid] = 0.f;
            g_Qa[N_ATTRS + tid] = 0.f;
        }
        // zero g_vt pad columns j in [5000, 5056) for all 128 f-rows
        u32* vt32 = (u32*)g_vt;
        for (int idx = tid; idx < 128 * 28; idx += 256) {
            int f = idx / 28, c = idx % 28;
            vt32[((size_t)f * VT_LD + N_ATTRS) / 2 + c] = 0u;
        }
    }
}

// ================= K1: attr_h = attr_emb @ W ; Q,Qa ; V^T fp16 ; qmax =====
__global__ void k_attr(const float* __restrict__ ae, const float* __restrict__ Wm,
                       const float* __restrict__ a) {
    __shared__ float sA[64][32];
    __shared__ float sW[32][OUT_F];
    int tid = threadIdx.x;
    int r0 = blockIdx.x * 64;
    int wr = tid >> 5;
    int lane = tid & 31;
    float acc[8][4];
    #pragma unroll
    for (int i = 0; i < 8; i++)
        #pragma unroll
        for (int c = 0; c < 4; c++) acc[i][c] = 0.f;

    for (int k0 = 0; k0 < IN_F; k0 += 32) {
        __syncthreads();
        #pragma unroll
        for (int it = 0; it < 8; it++) {
            int idx = tid + 256 * it;
            int r = idx >> 5, kk = idx & 31;
            int gr = r0 + r;
            sA[r][kk] = (gr < N_ATTRS) ? ae[(size_t)gr * IN_F + k0 + kk] : 0.f;
        }
        #pragma unroll
        for (int it = 0; it < 4; it++) {
            int idx = tid + 256 * it;
            int kk = idx >> 5, f4 = idx & 31;
            *(float4*)&sW[kk][f4 * 4] = *(const float4*)(Wm + (size_t)(k0 + kk) * OUT_F + f4 * 4);
        }
        __syncthreads();
        #pragma unroll 8
        for (int kk = 0; kk < 32; kk++) {
            float4 wv = *(float4*)&sW[kk][lane * 4];
            #pragma unroll
            for (int r = 0; r < 8; r++) {
                float av = sA[wr * 8 + r][kk];
                acc[r][0] += av * wv.x;
                acc[r][1] += av * wv.y;
                acc[r][2] += av * wv.z;
                acc[r][3] += av * wv.w;
            }
        }
    }
    // V^T fp16: thread owns cols f = lane*4..+3, rows j = r0+wr*8 .. +7
    #pragma unroll
    for (int c = 0; c < 4; c++) {
        u32 p[4];
        #pragma unroll
        for (int k = 0; k < 4; k++)
            p[k] = cvt_f16x2(acc[2 * k][c], acc[2 * k + 1][c]);
        int jbase = r0 + wr * 8;
        if (jbase < N_ATTRS) {
            size_t off = (size_t)(lane * 4 + c) * VT_LD + jbase;
            *(uint4*)&g_vt[off] = make_uint4(p[0], p[1], p[2], p[3]);
        }
    }
    // scores
    float4 a2v = *(const float4*)(a + OUT_F + lane * 4);
    float qmax = 0.f;
    #pragma unroll
    for (int r = 0; r < 8; r++) {
        int gr = r0 + wr * 8 + r;
        float t = acc[r][0] * a2v.x + acc[r][1] * a2v.y + acc[r][2] * a2v.z + acc[r][3] * a2v.w;
        #pragma unroll
        for (int o = 16; o > 0; o >>= 1) t += __shfl_xor_sync(0xffffffffu, t, o);
        if (gr < N_ATTRS) {
            float Q = expf(t);
            if (lane == 0) {
                g_Q[gr]  = Q;
                g_Qa[gr] = expf(LRELU_ALPHA * t);
            }
            if (Q > qmax) qmax = Q;
        }
    }
    if (lane == 0) atomicMax(&g_qmax_i, __float_as_int(qmax));
}

// ================= K2: node scores -> scaled P, Pa, sc =================
__global__ void k_node(const float* __restrict__ ne) {
    int gw = (blockIdx.x * blockDim.x + threadIdx.x) >> 5;
    int lane = threadIdx.x & 31;
    if (gw >= N_NODES) return;
    const float4* row = (const float4*)(ne + (size_t)gw * IN_F);
    const float4* v1 = (const float4*)g_v1;
    float s = 0.f;
    #pragma unroll
    for (int t = 0; t < 4; t++) {
        float4 x = row[lane + 32 * t];
        float4 c = v1[lane + 32 * t];
        s += x.x * c.x + x.y * c.y + x.z * c.z + x.w * c.w;
    }
    #pragma unroll
    for (int o = 16; o > 0; o >>= 1) s += __shfl_xor_sync(0xffffffffu, s, o);
    if (lane == 0) {
        float P  = expf(s);
        float Pa = expf(LRELU_ALPHA * s);
        float Qmax = __int_as_float(g_qmax_i);
        float wmax = P * Qmax;
        if (wmax < 1.f) wmax = 1.f;
        float sc = 1.f / wmax;
        g_P[gw]  = P * sc;
        g_Pa[gw] = Pa * sc;
        g_sc[gw] = sc;
    }
}

// ================= K3: fp16 HMMA fused attention (split-j partials) =========
// CTA = 128 nodes x 128 feats x <=20 contiguous 64-attr tiles. 8 warps.
// feat + V bulk-streamed via cp.async (2-stage, 1 barrier/tile).
// Weight chains software-pipelined ONE SLICE AHEAD of their MMA phase
// (ping-pong fragment regs) so the weight dependency chain hides under
// the previous slice's MMA issue stream.
__global__ __launch_bounds__(256, 2) void k_mainT(const int* __restrict__ feat) {
    extern __shared__ char dsm[];
    const u32 smB = smem_u32(dsm);           // V tiles
    const u32 smF = smB + SMF_OFF;           // feat tiles
    float* sQQ = (float*)(dsm + SQQ_OFF);    // interleaved (q, qa) pairs
    const int tid = threadIdx.x;
    const int wid = tid >> 5, lane = tid & 31;
    const int js = blockIdx.x & 3;
    const int n0 = (blockIdx.x >> 2) * M_TILE;
    const int t0 = js * TPS;
    const int NT = (NT_J - t0 < TPS) ? (NT_J - t0) : TPS;
    const int jg0 = t0 * JT;                // contiguous split base

    // stage interleaved Q/Qa for this split
    for (int idx = tid; idx < NT * JT; idx += 256) {
        sQQ[2 * idx]     = g_Q[jg0 + idx];
        sQQ[2 * idx + 1] = g_Qa[jg0 + idx];
    }

    const int rrow = wid * 16 + (lane >> 2);   // local row 0..127
    const int r0 = n0 + rrow;
    const int r1 = r0 + 8;
    const int cq = (lane & 3) * 2;
    const bool v0 = r0 < N_NODES, v1 = r1 < N_NODES;
    const float P0  = v0 ? g_P[r0]  : 0.f;
    const float Pa0 = v0 ? g_Pa[r0] : 0.f;
    const float s0  = v0 ? g_sc[r0] : 1.f;
    const float P1  = v1 ? g_P[r1]  : 0.f;
    const float Pa1 = v1 ? g_Pa[r1] : 0.f;
    const float s1  = v1 ? g_sc[r1] : 1.f;

    float acc[16][4];
    #pragma unroll
    for (int i = 0; i < 16; i++)
        #pragma unroll
        for (int c = 0; c < 4; c++) acc[i][c] = 0.f;
    float den0 = 0.f, den1 = 0.f;

    const u32 lmoff = (u32)(((lane & 7) + ((lane & 16) >> 1)) * VROW + ((lane & 8) >> 3) * 16);
    // feat LDS addressing (row pitch 256B, chunk XOR row&7 swizzle)
    const u32 frow0 = (u32)(rrow * 256);
    const int xr = rrow & 7;                  // same for rrow and rrow+8
    const u32 boff = (u32)((cq & 2) << 2);    // byte offset within 16B chunk
    const int cbase = cq >> 2;                // chunk sub-index from cq

    auto loadV = [&](int kt) {
        const int j0 = jg0 + kt * JT;
        const u32 dst = smB + (kt & 1) * VTILE;
        #pragma unroll
        for (int t = 0; t < 4; t++) {
            int id = tid + 256 * t;          // 1024 chunks of 16B
            int f = id >> 3, c = id & 7;
            cp_async16(dst + (u32)(f * VROW + c * 16),
                       g_vt + (size_t)f * VT_LD + j0 + c * 8);
        }
    };
    auto loadF = [&](int kt) {
        const int j0 = jg0 + kt * JT;
        const u32 dst = smF + (kt & 1) * FTILE;
        #pragma unroll
        for (int t = 0; t < 8; t++) {
            int id = tid + 256 * t;          // 2048 chunks of 16B
            int row = id >> 4, chunk = id & 15;
            int gr = n0 + row;
            if (gr >= N_NODES) gr = N_NODES - 1;   // clamp: no fault, data unused
            int col = j0 + chunk * 4;
            if (col + 4 > N_ATTRS) col = j0;       // clamp pad cols (q=0 anyway)
            cp_async16(dst + (u32)(row * 256 + ((chunk ^ (row & 7)) << 4)),
                       feat + (size_t)gr * N_ATTRS + col);
        }
    };
    // feat mask LDS for slice ks of current tile into parity regs
    auto ldsF = [&](u32 fb, int ks, int2* pm) {
        int c0 = ks * 4 + cbase;
        u32 a00 = fb + frow0 + (u32)(((c0 ^ xr) << 4)) + boff;
        u32 a08 = fb + frow0 + (u32)((((c0 + 2) ^ xr) << 4)) + boff;
        asm volatile("ld.shared.v2.u32 {%0,%1}, [%2];" : "=r"(pm[0].x), "=r"(pm[0].y) : "r"(a00));
        asm volatile("ld.shared.v2.u32 {%0,%1}, [%2];" : "=r"(pm[1].x), "=r"(pm[1].y) : "r"(a08));
        asm volatile("ld.shared.v2.u32 {%0,%1}, [%2];" : "=r"(pm[2].x), "=r"(pm[2].y) : "r"(a00 + 2048));
        asm volatile("ld.shared.v2.u32 {%0,%1}, [%2];" : "=r"(pm[3].x), "=r"(pm[3].y) : "r"(a08 + 2048));
    };
    // weight chain for slice s of tile kt -> cvt'd fragments aO[4] (non-volatile)
    auto computeW = [&](int kt, int s, const int2* mm, u32* aO) {
        const int jl = kt * JT + s * 16 + cq;
        const float4 qq0 = *(const float4*)&sQQ[2 * jl];
        const float4 qq8 = *(const float4*)&sQQ[2 * (jl + 8)];
        float w00 = wfun(mm[0].x, P0, Pa0, s0, qq0.x, qq0.y);
        float w01 = wfun(mm[0].y, P0, Pa0, s0, qq0.z, qq0.w);
        float w08 = wfun(mm[1].x, P0, Pa0, s0, qq8.x, qq8.y);
        float w09 = wfun(mm[1].y, P0, Pa0, s0, qq8.z, qq8.w);
        float w10 = wfun(mm[2].x, P1, Pa1, s1, qq0.x, qq0.y);
        float w11 = wfun(mm[2].y, P1, Pa1, s1, qq0.z, qq0.w);
        float w18 = wfun(mm[3].x, P1, Pa1, s1, qq8.x, qq8.y);
        float w19 = wfun(mm[3].y, P1, Pa1, s1, qq8.z, qq8.w);
        den0 += (w00 + w01) + (w08 + w09);
        den1 += (w10 + w11) + (w18 + w19);
        aO[0] = cvt_f16x2(w00, w01);
        aO[1] = cvt_f16x2(w10, w11);
        aO[2] = cvt_f16x2(w08, w09);
        aO[3] = cvt_f16x2(w18, w19);
    };
    // MMA phase for slice ks using fragments a[4]
    auto mmaSlice = [&](u32 vb, int ks, const u32* a) {
        const u32 bbase = vb + lmoff + ks * 32;
        u32 br[3][4];
        LDSM4(br[0][0], br[0][1], br[0][2], br[0][3], bbase);
        LDSM4(br[1][0], br[1][1], br[1][2], br[1][3], bbase + 16 * VROW);
        #pragma unroll
        for (int np = 0; np < 8; np++) {
            const int cur = np % 3;
            if (np < 6) {
                const int nxt = (np + 2) % 3;
                LDSM4(br[nxt][0], br[nxt][1], br[nxt][2], br[nxt][3],
                      bbase + (np + 2) * 16 * VROW);
            }
            mma16816(acc[2 * np],     a[0], a[1], a[2], a[3], br[cur][0], br[cur][1]);
            mma16816(acc[2 * np + 1], a[0], a[1], a[2], a[3], br[cur][2], br[cur][3]);
        }
    };

    // prologue: stage tile 0
    loadF(0); loadV(0); CP_COMMIT();
    int2 pmA[4], pmB[4];
    u32 aP[2][4];

    for (int kt = 0; kt < NT; kt++) {
        asm volatile("cp.async.wait_group 0;" ::: "memory");
        __syncthreads();                 // single barrier per tile
        if (kt + 1 < NT) { loadF(kt + 1); loadV(kt + 1); CP_COMMIT(); }

        const u32 vb = smB + (kt & 1) * VTILE;
        const u32 fb = smF + (kt & 1) * FTILE;

        // two weight chains in flight before the first MMA
        ldsF(fb, 0, pmA);
        ldsF(fb, 1, pmB);
        computeW(kt, 0, pmA, aP[0]);
        ldsF(fb, 2, pmA);
        computeW(kt, 1, pmB, aP[1]);
        ldsF(fb, 3, pmB);

        mmaSlice(vb, 0, aP[0]);
        computeW(kt, 2, pmA, aP[0]);     // overwrites aP[0] after slice-0 MMAs
        mmaSlice(vb, 1, aP[1]);
        computeW(kt, 3, pmB, aP[1]);
        mmaSlice(vb, 2, aP[0]);
        mmaSlice(vb, 3, aP[1]);
    }

    // denominator partials (4 lanes share each row)
    den0 += __shfl_xor_sync(0xffffffffu, den0, 1);
    den0 += __shfl_xor_sync(0xffffffffu, den0, 2);
    den1 += __shfl_xor_sync(0xffffffffu, den1, 1);
    den1 += __shfl_xor_sync(0xffffffffu, den1, 2);
    if ((lane & 3) == 0) {
        if (v0) g_den[js * N_NODES + r0] = den0;
        if (v1) g_den[js * N_NODES + r1] = den1;
    }
    // accumulator partials
    float* pb = g_part + (size_t)js * N_NODES * OUT_F;
    #pragma unroll
    for (int np = 0; np < 16; np++) {
        int col = np * 8 + cq;
        if (v0) *(float2*)(pb + (size_t)r0 * OUT_F + col) = make_float2(acc[np][0], acc[np][1]);
        if (v1) *(float2*)(pb + (size_t)r1 * OUT_F + col) = make_float2(acc[np][2], acc[np][3]);
    }
}

// ================= K4: reduce splits, normalize, ELU, store =================
__global__ void k_final(float* __restrict__ out) {
    int gid = blockIdx.x * blockDim.x + threadIdx.x;   // one float4 each
    int row = gid >> 5;
    int f = (gid & 31) * 4;
    if (row >= N_NODES) return;
    float4 s = make_float4(0.f, 0.f, 0.f, 0.f);
    float den = 0.f;
    #pragma unroll
    for (int sp = 0; sp < JSPLIT; sp++) {
        const float4 p = *(const float4*)(g_part + ((size_t)sp * N_NODES + row) * OUT_F + f);
        s.x += p.x; s.y += p.y; s.z += p.z; s.w += p.w;
        den += g_den[sp * N_NODES + row];
    }
    float inv = (den > 0.f) ? 1.f / den : 0.f;
    float o[4] = {s.x * inv, s.y * inv, s.z * inv, s.w * inv};
    #pragma unroll
    for (int e = 0; e < 4; e++) o[e] = (o[e] > 0.f) ? o[e] : expm1f(o[e]);
    *(float4*)(out + (size_t)row * OUT_F + f) = make_float4(o[0], o[1], o[2], o[3]);
}

extern "C" void kernel_launch(void* const* d_in, const int* in_sizes, int n_in,
                              void* d_out, int out_size) {
    const float* node_emb = (const float*)d_in[0];
    const float* attr_emb = (const float*)d_in[1];
    const int*   feat     = (const int*)d_in[2];
    const float* W        = (const float*)d_in[3];
    const float* a        = (const float*)d_in[4];
    float* out = (float*)d_out;

    cudaFuncSetAttribute(k_mainT, cudaFuncAttributeMaxDynamicSharedMemorySize, SMEM_BYTES);

    k_v1<<<(IN_F + 255) / 256, 256>>>(W, a);                 // idx 0
    k_attr<<<(N_ATTRS + 63) / 64, 256>>>(attr_emb, W, a);    // idx 1
    k_node<<<(N_NODES * 32 + 255) / 256, 256>>>(node_emb);   // idx 2
    k_mainT<<<N_CTAS_N * JSPLIT, 256, SMEM_BYTES>>>(feat);   // idx 3 (profiled)
    k_final<<<(N_NODES * 32 + 255) / 256, 256>>>(out);       // idx 4
}